// round 12
// baseline (speedup 1.0000x reference)
#include <cuda_runtime.h>
#include <cuda_bf16.h>
#include <stdint.h>

#define DINLINE __device__ __forceinline__

DINLINE uint32_t smem_u32(const void* p) {
    uint32_t a;
    asm("{ .reg .u64 t; cvta.to.shared.u64 t, %1; cvt.u32.u64 %0, t; }" : "=r"(a) : "l"(p));
    return a;
}

DINLINE void ldsm_x4(uint32_t addr, uint32_t* r) {
    asm volatile("ldmatrix.sync.aligned.m8n8.x4.shared.b16 {%0,%1,%2,%3}, [%4];"
                 : "=r"(r[0]), "=r"(r[1]), "=r"(r[2]), "=r"(r[3]) : "r"(addr));
}

DINLINE void mma16816(float* d, const uint32_t* a, const uint32_t* b) {
    asm volatile("mma.sync.aligned.m16n8k16.row.col.f32.bf16.bf16.f32 "
                 "{%0,%1,%2,%3}, {%4,%5,%6,%7}, {%8,%9}, {%0,%1,%2,%3};"
                 : "+f"(d[0]), "+f"(d[1]), "+f"(d[2]), "+f"(d[3])
                 : "r"(a[0]), "r"(a[1]), "r"(a[2]), "r"(a[3]), "r"(b[0]), "r"(b[1]));
}

DINLINE void imma16832(int* d, const uint32_t* a, const uint32_t* b) {
    asm volatile("mma.sync.aligned.m16n8k32.row.col.s32.s8.s8.s32 "
                 "{%0,%1,%2,%3}, {%4,%5,%6,%7}, {%8,%9}, {%0,%1,%2,%3};"
                 : "+r"(d[0]), "+r"(d[1]), "+r"(d[2]), "+r"(d[3])
                 : "r"(a[0]), "r"(a[1]), "r"(a[2]), "r"(a[3]), "r"(b[0]), "r"(b[1]));
}

DINLINE void cp16(uint32_t saddr, const void* g) {
    asm volatile("cp.async.cg.shared.global [%0], [%1], 16;" :: "r"(saddr), "l"(g));
}
DINLINE void cp_commit() { asm volatile("cp.async.commit_group;" ::: "memory"); }
DINLINE void cp_wait0() { asm volatile("cp.async.wait_group 0;" ::: "memory"); }
DINLINE void cp_wait1() { asm volatile("cp.async.wait_group 1;" ::: "memory"); }
DINLINE void cp_wait2() { asm volatile("cp.async.wait_group 2;" ::: "memory"); }

DINLINE void split2(float a, float b, __nv_bfloat162& h, __nv_bfloat162& l) {
    h = __floats2bfloat162_rn(a, b);
    l = __floats2bfloat162_rn(a - __low2float(h), b - __high2float(h));
}

DINLINE int clampi(int v, int lo, int hi) { return v < lo ? lo : (v > hi ? hi : v); }

// ======================= scratch (no allocs) =======================
__device__ __align__(16) __nv_bfloat16 g_e128h[1024 * 128];
__device__ __align__(16) __nv_bfloat16 g_e128l[1024 * 128];
__device__ __align__(16) __nv_bfloat16 g_e256h[1024 * 256];
__device__ __align__(16) __nv_bfloat16 g_e256l[1024 * 256];
__device__ __align__(16) __nv_bfloat16 g_r1wh[256 * 128];
__device__ __align__(16) __nv_bfloat16 g_r1wl[256 * 128];
__device__ __align__(16) __nv_bfloat16 g_r2wh[512 * 256];
__device__ __align__(16) __nv_bfloat16 g_r2wl[512 * 256];
__device__ __align__(16) float  g_e512f[1024 * 512];
__device__ __align__(16) int8_t g_e512q1[1024 * 512];
__device__ __align__(16) int8_t g_e512q2[1024 * 512];
__device__ __align__(16) float  g_e1024f[1024 * 1024];
__device__ __align__(16) int8_t g_e1024q1[1024 * 1024];
__device__ __align__(16) int8_t g_e1024q2[1024 * 1024];
__device__ __align__(16) int8_t g_r3wq1[1024 * 512];
__device__ __align__(16) int8_t g_r3wq2[1024 * 512];
__device__ __align__(16) int8_t g_wabq1[1024 * 1024];
__device__ __align__(16) int8_t g_wabq2[1024 * 1024];
__device__ __align__(16) float  g_swr3[1024];
__device__ __align__(16) float  g_sww1[1024];
__device__ int g_amax[2];                      // [0]=e512, [1]=e1024 (as float bits)
__device__ __align__(16) float g_AB[1024 * 1024];
__device__ __align__(16) float g_m[16 * 512];

// ======================= zero amax =======================
__global__ void zero_kernel(int* amax) {
    if (threadIdx.x < 2) amax[threadIdx.x] = 0;
}

// ======================= prep: bf16 splits + embed + int8 weight quant =======================
DINLINE void split_store4(const float4* __restrict__ src, __nv_bfloat162* __restrict__ h,
                          __nv_bfloat162* __restrict__ l, int i) {
    float4 v = src[i];
    __nv_bfloat162 h0, l0, h1, l1;
    split2(v.x, v.y, h0, l0);
    split2(v.z, v.w, h1, l1);
    h[2 * i] = h0; h[2 * i + 1] = h1;
    l[2 * i] = l0; l[2 * i + 1] = l1;
}

// blocks: [0,32) r1w split, [32,160) r2w split, [160,672) embed,
//         [672,1696) r3w row-quant (1024 rows, K=512), [1696,2720) w1 row-quant (1024 rows, K=1024)
__global__ __launch_bounds__(256) void prep_kernel(
    const float* __restrict__ r1w, __nv_bfloat162* __restrict__ r1h, __nv_bfloat162* __restrict__ r1l,
    const float* __restrict__ r2w, __nv_bfloat162* __restrict__ r2h, __nv_bfloat162* __restrict__ r2l,
    const float* __restrict__ r3w, int8_t* __restrict__ r3q1, int8_t* __restrict__ r3q2,
    float* __restrict__ swr3,
    const float* __restrict__ w1, int8_t* __restrict__ wq1, int8_t* __restrict__ wq2,
    float* __restrict__ sww1,
    const float* __restrict__ x,
    const float* __restrict__ e1w, const float* __restrict__ e1b,
    const float* __restrict__ e2w, const float* __restrict__ e2b,
    __nv_bfloat16* __restrict__ oh, __nv_bfloat16* __restrict__ ol) {
    __shared__ float red[256];
    __shared__ float xr[2][16];
    int b = blockIdx.x, tid = threadIdx.x;
    if (b < 32) {
        split_store4((const float4*)r1w, r1h, r1l, b * 256 + tid);
    } else if (b < 160) {
        split_store4((const float4*)r2w, r2h, r2l, (b - 32) * 256 + tid);
    } else if (b < 672) {
        int rb = tid >> 7;
        int t = tid & 127;
        int row = (b - 160) * 2 + rb;
        if (t < 16) xr[rb][t] = x[row * 16 + t];
        __syncthreads();
        float s1 = e1b[t];
#pragma unroll
        for (int c = 0; c < 3; c++) s1 = fmaf(xr[rb][c], e1w[t * 3 + c], s1);
        float s2 = e2b[t];
#pragma unroll
        for (int c = 0; c < 13; c++) s2 = fmaf(xr[rb][3 + c], e2w[t * 13 + c], s2);
        float v = fmaxf(s1, 0.f) + fmaxf(s2, 0.f);
        __nv_bfloat16 h = __float2bfloat16(v);
        oh[row * 128 + t] = h;
        ol[row * 128 + t] = __float2bfloat16(v - __bfloat162float(h));
    } else if (b < 1696) {
        // r3w row quant: row n, K=512, 2 elems/thread
        int n = b - 672;
        float2 w = *(const float2*)(r3w + (size_t)n * 512 + tid * 2);
        float lmax = fmaxf(fabsf(w.x), fabsf(w.y));
        red[tid] = lmax;
        __syncthreads();
        for (int s = 128; s > 0; s >>= 1) {
            if (tid < s) red[tid] = fmaxf(red[tid], red[tid + s]);
            __syncthreads();
        }
        float amax = red[0];
        float sw = (amax > 0.f) ? amax / 127.f : 1.f;
        if (tid == 0) swr3[n] = sw;
        float inv = 1.f / sw;
        size_t o = (size_t)n * 512 + tid * 2;
#pragma unroll
        for (int j = 0; j < 2; ++j) {
            float q = (j ? w.y : w.x) * inv;
            int q1 = clampi(__float2int_rn(q), -127, 127);
            int q2 = clampi(__float2int_rn((q - (float)q1) * 256.f), -127, 127);
            r3q1[o + j] = (int8_t)q1;
            r3q2[o + j] = (int8_t)q2;
        }
    } else {
        // w1 combined row quant: row n, K=1024, 4 elems/thread
        int n = b - 1696;
        const float* src = (n < 512) ? (w1 + (size_t)n * 2048 + tid * 4)
                                     : (w1 + (size_t)(n - 512) * 2048 + 1024 + tid * 4);
        float4 w = *(const float4*)src;
        float lmax = fmaxf(fmaxf(fabsf(w.x), fabsf(w.y)), fmaxf(fabsf(w.z), fabsf(w.w)));
        red[tid] = lmax;
        __syncthreads();
        for (int s = 128; s > 0; s >>= 1) {
            if (tid < s) red[tid] = fmaxf(red[tid], red[tid + s]);
            __syncthreads();
        }
        float amax = red[0];
        float sw = (amax > 0.f) ? amax / 127.f : 1.f;
        if (tid == 0) sww1[n] = sw;
        float inv = 1.f / sw;
        float wv[4] = {w.x, w.y, w.z, w.w};
        uint32_t p1 = 0, p2 = 0;
#pragma unroll
        for (int j = 0; j < 4; ++j) {
            float q = wv[j] * inv;
            int q1 = clampi(__float2int_rn(q), -127, 127);
            int q2 = clampi(__float2int_rn((q - (float)q1) * 256.f), -127, 127);
            p1 |= ((uint32_t)(uint8_t)(int8_t)q1) << (8 * j);
            p2 |= ((uint32_t)(uint8_t)(int8_t)q2) << (8 * j);
        }
        size_t o = (size_t)n * 1024 + tid * 4;
        *(uint32_t*)(wq1 + o) = p1;
        *(uint32_t*)(wq2 + o) = p2;
    }
}

// ======================= activation quantize: fp32 -> 2x int8 slices =======================
__global__ __launch_bounds__(256) void quant_kernel(const float* __restrict__ xf,
                                                    const int* __restrict__ amaxp,
                                                    int8_t* __restrict__ q1o,
                                                    int8_t* __restrict__ q2o) {
    int i = blockIdx.x * 256 + threadIdx.x;   // over float4 groups
    float amax = __int_as_float(__ldg(amaxp));
    float sa = (amax > 0.f) ? amax / 127.f : 1.f;
    float inv = 1.f / sa;
    float4 v = *(const float4*)(xf + (size_t)i * 4);
    float xv[4] = {v.x, v.y, v.z, v.w};
    uint32_t p1 = 0, p2 = 0;
#pragma unroll
    for (int j = 0; j < 4; ++j) {
        float q = xv[j] * inv;                 // x >= 0 (relu)
        int q1 = clampi(__float2int_rn(q), 0, 127);
        int q2 = clampi(__float2int_rn((q - (float)q1) * 256.f), -127, 127);
        p1 |= ((uint32_t)(uint8_t)(int8_t)q1) << (8 * j);
        p2 |= ((uint32_t)(uint8_t)(int8_t)q2) << (8 * j);
    }
    *(uint32_t*)(q1o + (size_t)i * 4) = p1;
    *(uint32_t*)(q2o + (size_t)i * 4) = p2;
}

static constexpr int GSTRIDE = 144;   // bf16 path: 64 bf16 = 128B + 16B pad

// ======================= bf16 GEMM (r1/r2): 64x64 tile, 128 thr, 4-stage =======================
// OUTM==1: bias+relu -> split bf16. OUTM==2: bias+relu -> fp32 + tensor absmax (atomic).
static constexpr int S_OFF_AL = 64 * GSTRIDE;
static constexpr int S_OFF_WH = 128 * GSTRIDE;
static constexpr int S_OFF_WL = S_OFF_WH + 64 * GSTRIDE;
static constexpr int S_STAGE = S_OFF_WL + 64 * GSTRIDE;   // 36864
static constexpr int S_SMEM = 4 * S_STAGE;                // 147456

template <int OUTM>
__global__ __launch_bounds__(128) void mma_gemm_small(
    const __nv_bfloat16* __restrict__ Ah, const __nv_bfloat16* __restrict__ Al,
    const __nv_bfloat16* __restrict__ Wh, const __nv_bfloat16* __restrict__ Wl,
    const float* __restrict__ bias, int K,
    __nv_bfloat16* __restrict__ outH, __nv_bfloat16* __restrict__ outL,
    float* __restrict__ outF, int* __restrict__ amaxp, int ldo) {
    extern __shared__ char smc[];
    __shared__ float warpmax[4];
    uint32_t sbase = smem_u32(smc);

    int tid = threadIdx.x, lane = tid & 31, wid = tid >> 5;
    int mw = wid >> 1, nw = wid & 1;
    int m0 = blockIdx.y * 64, n0 = blockIdx.x * 64;

    float acc[2][4][4] = {};

    uint32_t aoff = (lane & 15) * GSTRIDE + ((lane >> 4) << 4);
    uint32_t boff = ((((lane >> 4) << 3) + (lane & 7)) * GSTRIDE) + (((lane >> 3) & 1) << 4);
    uint32_t aBase0 = sbase + mw * 32 * GSTRIDE + aoff;
    uint32_t bBase0 = sbase + S_OFF_WH + nw * 32 * GSTRIDE + boff;

    int lrow = tid >> 3, lu = tid & 7;
    uint32_t sAh = sbase, sAl = sbase + S_OFF_AL, sWh = sbase + S_OFF_WH, sWl = sbase + S_OFF_WL;

    int nc = K >> 6;
    auto load_stage = [&](int c) {
        int k0 = c << 6;
        uint32_t so = (uint32_t)(c & 3) * S_STAGE;
#pragma unroll
        for (int q = 0; q < 4; ++q) {
            int row = lrow + q * 16;
            size_t goA = (size_t)(m0 + row) * K + k0 + lu * 8;
            size_t goW = (size_t)(n0 + row) * K + k0 + lu * 8;
            uint32_t sro = row * GSTRIDE + lu * 16 + so;
            cp16(sAh + sro, Ah + goA);
            cp16(sAl + sro, Al + goA);
            cp16(sWh + sro, Wh + goW);
            cp16(sWl + sro, Wl + goW);
        }
        cp_commit();
    };

    int issued = (nc < 3) ? nc : 3;
    for (int c = 0; c < issued; ++c) load_stage(c);

    for (int c = 0; c < nc; ++c) {
        int w = issued - c - 1;
        if (w <= 0) cp_wait0(); else if (w == 1) cp_wait1(); else cp_wait2();
        __syncthreads();
        if (issued < nc) { load_stage(issued); ++issued; }

        uint32_t so = (uint32_t)(c & 3) * S_STAGE;
        uint32_t aBase = aBase0 + so, bBase = bBase0 + so;
#pragma unroll
        for (int kk = 0; kk < 4; ++kk) {
            uint32_t ah[2][4], al[2][4], bh[4][2], bl[4][2];
#pragma unroll
            for (int mi = 0; mi < 2; ++mi) {
                ldsm_x4(aBase + mi * (16 * GSTRIDE) + kk * 32, ah[mi]);
                ldsm_x4(aBase + S_OFF_AL + mi * (16 * GSTRIDE) + kk * 32, al[mi]);
            }
#pragma unroll
            for (int p = 0; p < 2; ++p) {
                uint32_t r4[4];
                ldsm_x4(bBase + p * (16 * GSTRIDE) + kk * 32, r4);
                bh[2 * p][0] = r4[0]; bh[2 * p][1] = r4[1];
                bh[2 * p + 1][0] = r4[2]; bh[2 * p + 1][1] = r4[3];
                ldsm_x4(bBase + (S_OFF_WL - S_OFF_WH) + p * (16 * GSTRIDE) + kk * 32, r4);
                bl[2 * p][0] = r4[0]; bl[2 * p][1] = r4[1];
                bl[2 * p + 1][0] = r4[2]; bl[2 * p + 1][1] = r4[3];
            }
#pragma unroll
            for (int mi = 0; mi < 2; ++mi)
#pragma unroll
                for (int ni = 0; ni < 4; ++ni)
                    mma16816(acc[mi][ni], ah[mi], bh[ni]);
#pragma unroll
            for (int mi = 0; mi < 2; ++mi)
#pragma unroll
                for (int ni = 0; ni < 4; ++ni)
                    mma16816(acc[mi][ni], ah[mi], bl[ni]);
#pragma unroll
            for (int mi = 0; mi < 2; ++mi)
#pragma unroll
                for (int ni = 0; ni < 4; ++ni)
                    mma16816(acc[mi][ni], al[mi], bh[ni]);
        }
    }

    int r = lane >> 2, c2 = (lane & 3) * 2;
    int warpM = m0 + mw * 32, warpN = n0 + nw * 32;
    float tmax = 0.f;
#pragma unroll
    for (int mi = 0; mi < 2; ++mi)
#pragma unroll
        for (int ni = 0; ni < 4; ++ni) {
            int n = warpN + ni * 8 + c2;
#pragma unroll
            for (int h = 0; h < 2; ++h) {
                int m = warpM + mi * 16 + r + h * 8;
                float2 bb = *(const float2*)(bias + n);
                float v0 = fmaxf(acc[mi][ni][h * 2 + 0] + bb.x, 0.f);
                float v1 = fmaxf(acc[mi][ni][h * 2 + 1] + bb.y, 0.f);
                if (OUTM == 1) {
                    __nv_bfloat162 hh, ll;
                    split2(v0, v1, hh, ll);
                    *(__nv_bfloat162*)(outH + (size_t)m * ldo + n) = hh;
                    *(__nv_bfloat162*)(outL + (size_t)m * ldo + n) = ll;
                } else {
                    *(float2*)(outF + (size_t)m * ldo + n) = make_float2(v0, v1);
                    tmax = fmaxf(tmax, fmaxf(v0, v1));
                }
            }
        }
    if (OUTM == 2) {
#pragma unroll
        for (int s = 16; s > 0; s >>= 1) tmax = fmaxf(tmax, __shfl_xor_sync(0xffffffffu, tmax, s));
        if (lane == 0) warpmax[wid] = tmax;
        __syncthreads();
        if (tid == 0) {
            float m = fmaxf(fmaxf(warpmax[0], warpmax[1]), fmaxf(warpmax[2], warpmax[3]));
            atomicMax(amaxp, __float_as_int(m));
        }
    }
}

// ======================= int8 IMMA GEMM (r3/AB): 128x64 tile, 256 thr, 4-stage ==========
// C = sa*sw[n]*(P11 + Pmix/256), A = q1 + q2/256 (per-tensor sa), W = q1 + q2/256 (per-row sw).
// OUTM==1: bias+relu -> fp32 + amax. OUTM==0: raw fp32.
static constexpr int ISTRIDE = 80;        // 64 int8 + 16B pad
static constexpr int I_A2 = 128 * ISTRIDE;            // 10240
static constexpr int I_W1 = 2 * I_A2;                  // 20480
static constexpr int I_W2 = I_W1 + 64 * ISTRIDE;       // 25600
static constexpr int I_STAGE = I_W2 + 64 * ISTRIDE;    // 30720
static constexpr int I_SMEM = 4 * I_STAGE;             // 122880

template <int OUTM>
__global__ __launch_bounds__(256) void imma_gemm(
    const int8_t* __restrict__ A1, const int8_t* __restrict__ A2,
    const int8_t* __restrict__ W1, const int8_t* __restrict__ W2,
    const float* __restrict__ sw, const int* __restrict__ amax_in,
    const float* __restrict__ bias, int K,
    float* __restrict__ outF, int* __restrict__ amax_out, int ldo) {
    extern __shared__ char smc[];
    __shared__ float warpmax[8];
    uint32_t sbase = smem_u32(smc);

    int tid = threadIdx.x, lane = tid & 31, wid = tid >> 5;
    int mw = wid >> 1, nw = wid & 1;          // 4x2 warps, warp tile 32x32
    int m0 = blockIdx.y * 128, n0 = blockIdx.x * 64;

    int acc11[2][4][4] = {};
    int accMx[2][4][4] = {};

    // ldsm lane addressing (int8 tiles, 16B half-K units)
    uint32_t arow = (lane & 7) + (((lane >> 3) & 1) << 3);   // row within 16
    uint32_t ahalf = (lane >> 4) & 1;                        // +16B (K 16..31)
    uint32_t brow = lane & 7;
    uint32_t bg = lane >> 3;
    uint32_t bnoff = (bg >> 1) << 3;                         // +8 n-rows
    uint32_t bhalf = bg & 1;                                 // +16B
    uint32_t aAdd = (mw * 32 + arow) * ISTRIDE + ahalf * 16;
    uint32_t bAdd = (nw * 32 + bnoff + brow) * ISTRIDE + bhalf * 16;

    int lrow = tid >> 2, lu = tid & 3;        // loader: 64 rows/pass, 16B units
    uint32_t sA1 = sbase, sA2 = sbase + I_A2, sW1 = sbase + I_W1, sW2 = sbase + I_W2;

    int nc = K >> 6;
    auto load_stage = [&](int c) {
        int k0 = c << 6;
        uint32_t so = (uint32_t)(c & 3) * I_STAGE;
#pragma unroll
        for (int q = 0; q < 2; ++q) {
            int row = lrow + q * 64;
            size_t go = (size_t)(m0 + row) * K + k0 + lu * 16;
            uint32_t sro = row * ISTRIDE + lu * 16 + so;
            cp16(sA1 + sro, A1 + go);
            cp16(sA2 + sro, A2 + go);
        }
        {
            int row = lrow;
            size_t go = (size_t)(n0 + row) * K + k0 + lu * 16;
            uint32_t sro = row * ISTRIDE + lu * 16 + so;
            cp16(sW1 + sro, W1 + go);
            cp16(sW2 + sro, W2 + go);
        }
        cp_commit();
    };

    int issued = (nc < 3) ? nc : 3;
    for (int c = 0; c < issued; ++c) load_stage(c);

    for (int c = 0; c < nc; ++c) {
        int w = issued - c - 1;
        if (w <= 0) cp_wait0(); else if (w == 1) cp_wait1(); else cp_wait2();
        __syncthreads();
        if (issued < nc) { load_stage(issued); ++issued; }

        uint32_t so = (uint32_t)(c & 3) * I_STAGE;
#pragma unroll
        for (int kk = 0; kk < 2; ++kk) {      // two K32 steps per 64-chunk
            uint32_t a1f[2][4], a2f[2][4], b1f[4][2], b2f[4][2];
#pragma unroll
            for (int mi = 0; mi < 2; ++mi) {
                uint32_t ad = sbase + so + aAdd + mi * (16 * ISTRIDE) + kk * 32;
                ldsm_x4(ad, a1f[mi]);
                ldsm_x4(ad + I_A2, a2f[mi]);
            }
#pragma unroll
            for (int p = 0; p < 2; ++p) {     // ni pairs {0,1},{2,3}
                uint32_t bd = sbase + so + I_W1 + bAdd + p * (16 * ISTRIDE) + kk * 32;
                uint32_t r4[4];
                ldsm_x4(bd, r4);
                b1f[2 * p][0] = r4[0]; b1f[2 * p][1] = r4[1];
                b1f[2 * p + 1][0] = r4[2]; b1f[2 * p + 1][1] = r4[3];
                ldsm_x4(bd + (I_W2 - I_W1), r4);
                b2f[2 * p][0] = r4[0]; b2f[2 * p][1] = r4[1];
                b2f[2 * p + 1][0] = r4[2]; b2f[2 * p + 1][1] = r4[3];
            }
#pragma unroll
            for (int mi = 0; mi < 2; ++mi)
#pragma unroll
                for (int ni = 0; ni < 4; ++ni)
                    imma16832(acc11[mi][ni], a1f[mi], b1f[ni]);
#pragma unroll
            for (int mi = 0; mi < 2; ++mi)
#pragma unroll
                for (int ni = 0; ni < 4; ++ni)
                    imma16832(accMx[mi][ni], a1f[mi], b2f[ni]);
#pragma unroll
            for (int mi = 0; mi < 2; ++mi)
#pragma unroll
                for (int ni = 0; ni < 4; ++ni)
                    imma16832(accMx[mi][ni], a2f[mi], b1f[ni]);
        }
    }

    float amaxv = __int_as_float(__ldg(amax_in));
    float sa = (amaxv > 0.f) ? amaxv / 127.f : 1.f;

    int r = lane >> 2, c2 = (lane & 3) * 2;
    int warpM = m0 + mw * 32, warpN = n0 + nw * 32;
    float tmax = 0.f;
#pragma unroll
    for (int mi = 0; mi < 2; ++mi)
#pragma unroll
        for (int ni = 0; ni < 4; ++ni) {
            int n = warpN + ni * 8 + c2;
            float s0 = sa * sw[n], s1 = sa * sw[n + 1];
#pragma unroll
            for (int h = 0; h < 2; ++h) {
                int m = warpM + mi * 16 + r + h * 8;
                float v0 = s0 * ((float)acc11[mi][ni][h * 2 + 0] +
                                 (float)accMx[mi][ni][h * 2 + 0] * (1.f / 256.f));
                float v1 = s1 * ((float)acc11[mi][ni][h * 2 + 1] +
                                 (float)accMx[mi][ni][h * 2 + 1] * (1.f / 256.f));
                if (OUTM == 1) {
                    float2 bb = *(const float2*)(bias + n);
                    v0 = fmaxf(v0 + bb.x, 0.f);
                    v1 = fmaxf(v1 + bb.y, 0.f);
                    tmax = fmaxf(tmax, fmaxf(v0, v1));
                }
                *(float2*)(outF + (size_t)m * ldo + n) = make_float2(v0, v1);
            }
        }
    if (OUTM == 1) {
#pragma unroll
        for (int s = 16; s > 0; s >>= 1) tmax = fmaxf(tmax, __shfl_xor_sync(0xffffffffu, tmax, s));
        if (lane == 0) warpmax[wid] = tmax;
        __syncthreads();
        if (tid == 0) {
            float m = warpmax[0];
#pragma unroll
            for (int i = 1; i < 8; ++i) m = fmaxf(m, warpmax[i]);
            atomicMax(amax_out, __float_as_int(m));
        }
    }
}

// ======================= pairwise relu outer-sum mean =======================
__global__ __launch_bounds__(256) void pairwise_kernel(const float* __restrict__ AB,
                                                       const float* __restrict__ b1,
                                                       float* __restrict__ mout) {
    __shared__ float As[64][64];
    __shared__ float Bs[64][64];
    __shared__ float part[4][64];
    int t = threadIdx.x;
    int chunk = blockIdx.x;
    int b = blockIdx.y;
    int c0 = chunk * 64;
    const float* base = AB + (size_t)b * 64 * 1024;

#pragma unroll
    for (int q = 0; q < 4; q++) {
        int idx = t + q * 256;
        int row = idx >> 4;
        int seg = idx & 15;
        float4 va = *(const float4*)(base + row * 1024 + c0 + seg * 4);
        float4 vb = *(const float4*)(base + row * 1024 + 512 + c0 + seg * 4);
        *(float4*)&As[row][seg * 4] = va;
        *(float4*)&Bs[row][seg * 4] = vb;
    }
    __syncthreads();

    int c = t & 63;
    int ig = t >> 6;
    float bias = b1[c0 + c];
    float acc = 0.f;
    for (int i = ig * 16; i < ig * 16 + 16; i++) {
        float bb = Bs[i][c] + bias;
#pragma unroll
        for (int j = 0; j < 64; j++)
            acc += fmaxf(As[j][c] + bb, 0.f);
    }
    part[ig][c] = acc;
    __syncthreads();
    if (t < 64) {
        float s = part[0][t] + part[1][t] + part[2][t] + part[3][t];
        mout[b * 512 + c0 + t] = s * (1.0f / 4096.0f);
    }
}

// ======================= final 512 -> 2048 =======================
__global__ __launch_bounds__(256) void final_kernel(const float* __restrict__ m,
                                                    const float* __restrict__ w2,
                                                    const float* __restrict__ b2,
                                                    float* __restrict__ out) {
    __shared__ float sm[16 * 512];
    int t = threadIdx.x;
    for (int i = t; i < 16 * 512; i += 256) sm[i] = m[i];
    __syncthreads();

    int warp = t >> 5, lane = t & 31;
    int o = blockIdx.x * 8 + warp;
    float acc[16];
#pragma unroll
    for (int b = 0; b < 16; b++) acc[b] = 0.f;
    const float* wrow = w2 + (size_t)o * 512;
#pragma unroll
    for (int kc = 0; kc < 16; kc++) {
        int k = kc * 32 + lane;
        float wv = wrow[k];
#pragma unroll
        for (int b = 0; b < 16; b++) acc[b] = fmaf(wv, sm[b * 512 + k], acc[b]);
    }
#pragma unroll
    for (int b = 0; b < 16; b++) {
        float v = acc[b];
#pragma unroll
        for (int s = 16; s > 0; s >>= 1) v += __shfl_xor_sync(0xffffffffu, v, s);
        if (lane == 0) out[b * 2048 + o] = v + b2[o];
    }
}

// ======================= launch =======================
extern "C" void kernel_launch(void* const* d_in, const int* in_sizes, int n_in,
                              void* d_out, int out_size) {
    (void)in_sizes; (void)n_in; (void)out_size;
    const float* x   = (const float*)d_in[0];
    const float* e1w = (const float*)d_in[1];
    const float* e1b = (const float*)d_in[2];
    const float* e2w = (const float*)d_in[3];
    const float* e2b = (const float*)d_in[4];
    const float* r1w = (const float*)d_in[5];
    const float* r1b = (const float*)d_in[6];
    const float* r2w = (const float*)d_in[7];
    const float* r2b = (const float*)d_in[8];
    const float* r3w = (const float*)d_in[9];
    const float* r3b = (const float*)d_in[10];
    const float* w1  = (const float*)d_in[11];
    const float* b1  = (const float*)d_in[12];
    const float* w2  = (const float*)d_in[13];
    const float* b2  = (const float*)d_in[14];
    float* out = (float*)d_out;

    __nv_bfloat16 *e128h, *e128l, *e256h, *e256l, *r1wh, *r1wl, *r2wh, *r2wl;
    float *e512f, *e1024f, *AB, *mbuf, *swr3, *sww1;
    int8_t *e512q1, *e512q2, *e1024q1, *e1024q2, *r3wq1, *r3wq2, *wabq1, *wabq2;
    int* amax;
    cudaGetSymbolAddress((void**)&e128h, g_e128h);
    cudaGetSymbolAddress((void**)&e128l, g_e128l);
    cudaGetSymbolAddress((void**)&e256h, g_e256h);
    cudaGetSymbolAddress((void**)&e256l, g_e256l);
    cudaGetSymbolAddress((void**)&r1wh, g_r1wh);
    cudaGetSymbolAddress((void**)&r1wl, g_r1wl);
    cudaGetSymbolAddress((void**)&r2wh, g_r2wh);
    cudaGetSymbolAddress((void**)&r2wl, g_r2wl);
    cudaGetSymbolAddress((void**)&e512f, g_e512f);
    cudaGetSymbolAddress((void**)&e512q1, g_e512q1);
    cudaGetSymbolAddress((void**)&e512q2, g_e512q2);
    cudaGetSymbolAddress((void**)&e1024f, g_e1024f);
    cudaGetSymbolAddress((void**)&e1024q1, g_e1024q1);
    cudaGetSymbolAddress((void**)&e1024q2, g_e1024q2);
    cudaGetSymbolAddress((void**)&r3wq1, g_r3wq1);
    cudaGetSymbolAddress((void**)&r3wq2, g_r3wq2);
    cudaGetSymbolAddress((void**)&wabq1, g_wabq1);
    cudaGetSymbolAddress((void**)&wabq2, g_wabq2);
    cudaGetSymbolAddress((void**)&swr3, g_swr3);
    cudaGetSymbolAddress((void**)&sww1, g_sww1);
    cudaGetSymbolAddress((void**)&amax, g_amax);
    cudaGetSymbolAddress((void**)&AB, g_AB);
    cudaGetSymbolAddress((void**)&mbuf, g_m);

    cudaFuncSetAttribute(mma_gemm_small<1>, cudaFuncAttributeMaxDynamicSharedMemorySize, S_SMEM);
    cudaFuncSetAttribute(mma_gemm_small<2>, cudaFuncAttributeMaxDynamicSharedMemorySize, S_SMEM);
    cudaFuncSetAttribute(imma_gemm<1>, cudaFuncAttributeMaxDynamicSharedMemorySize, I_SMEM);
    cudaFuncSetAttribute(imma_gemm<0>, cudaFuncAttributeMaxDynamicSharedMemorySize, I_SMEM);

    // 0) zero amax accumulators
    zero_kernel<<<1, 32>>>(amax);

    // 1) prep: bf16 splits (r1/r2), embed, int8 row-quant (r3w, w1-combined)
    prep_kernel<<<2720, 256>>>(r1w, (__nv_bfloat162*)r1wh, (__nv_bfloat162*)r1wl,
                               r2w, (__nv_bfloat162*)r2wh, (__nv_bfloat162*)r2wl,
                               r3w, r3wq1, r3wq2, swr3,
                               w1, wabq1, wabq2, sww1,
                               x, e1w, e1b, e2w, e2b, e128h, e128l);

    // 2) r1: 128 -> 256 bf16x3 (split bf16 out)
    mma_gemm_small<1><<<dim3(4, 16), 128, S_SMEM>>>(
        e128h, e128l, r1wh, r1wl, r1b, 128, e256h, e256l, nullptr, nullptr, 256);
    // 3) r2: 256 -> 512 bf16x3 (fp32 out + amax[0])
    mma_gemm_small<2><<<dim3(8, 16), 128, S_SMEM>>>(
        e256h, e256l, r2wh, r2wl, r2b, 256, nullptr, nullptr, e512f, amax, 512);
    // 4) quantize e512 -> int8 slices
    quant_kernel<<<512, 256>>>(e512f, amax, e512q1, e512q2);
    // 5) r3: 512 -> 1024 int8 IMMA (fp32 out + amax[1])
    imma_gemm<1><<<dim3(16, 8), 256, I_SMEM>>>(
        e512q1, e512q2, r3wq1, r3wq2, swr3, amax, r3b, 512, e1024f, amax + 1, 1024);
    // 6) quantize e1024
    quant_kernel<<<1024, 256>>>(e1024f, amax + 1, e1024q1, e1024q2);
    // 7) A|B fused: 1024 -> 1024 int8 IMMA (raw fp32)
    imma_gemm<0><<<dim3(16, 8), 256, I_SMEM>>>(
        e1024q1, e1024q2, wabq1, wabq2, sww1, amax + 1, nullptr, 1024, AB, nullptr, 1024);

    // 8) pairwise mean -> m[16][512]
    pairwise_kernel<<<dim3(8, 16), 256>>>(AB, b1, mbuf);
    // 9) final 512 -> 2048
    final_kernel<<<2048 / 8, 256>>>(mbuf, w2, b2, out);
}

// round 13
// speedup vs baseline: 1.9922x; 1.9922x over previous
#include <cuda_runtime.h>
#include <cuda_bf16.h>
#include <cuda_fp16.h>
#include <stdint.h>

#define DINLINE __device__ __forceinline__

DINLINE uint32_t smem_u32(const void* p) {
    uint32_t a;
    asm("{ .reg .u64 t; cvta.to.shared.u64 t, %1; cvt.u32.u64 %0, t; }" : "=r"(a) : "l"(p));
    return a;
}

DINLINE void ldsm_x4(uint32_t addr, uint32_t* r) {
    asm volatile("ldmatrix.sync.aligned.m8n8.x4.shared.b16 {%0,%1,%2,%3}, [%4];"
                 : "=r"(r[0]), "=r"(r[1]), "=r"(r[2]), "=r"(r[3]) : "r"(addr));
}

DINLINE void mma16816(float* d, const uint32_t* a, const uint32_t* b) {
    asm volatile("mma.sync.aligned.m16n8k16.row.col.f32.bf16.bf16.f32 "
                 "{%0,%1,%2,%3}, {%4,%5,%6,%7}, {%8,%9}, {%0,%1,%2,%3};"
                 : "+f"(d[0]), "+f"(d[1]), "+f"(d[2]), "+f"(d[3])
                 : "r"(a[0]), "r"(a[1]), "r"(a[2]), "r"(a[3]), "r"(b[0]), "r"(b[1]));
}

DINLINE void mma16816h(float* d, const uint32_t* a, const uint32_t* b) {
    asm volatile("mma.sync.aligned.m16n8k16.row.col.f32.f16.f16.f32 "
                 "{%0,%1,%2,%3}, {%4,%5,%6,%7}, {%8,%9}, {%0,%1,%2,%3};"
                 : "+f"(d[0]), "+f"(d[1]), "+f"(d[2]), "+f"(d[3])
                 : "r"(a[0]), "r"(a[1]), "r"(a[2]), "r"(a[3]), "r"(b[0]), "r"(b[1]));
}

DINLINE void cp16(uint32_t saddr, const void* g) {
    asm volatile("cp.async.cg.shared.global [%0], [%1], 16;" :: "r"(saddr), "l"(g));
}
DINLINE void cp_commit() { asm volatile("cp.async.commit_group;" ::: "memory"); }
DINLINE void cp_wait0() { asm volatile("cp.async.wait_group 0;" ::: "memory"); }
DINLINE void cp_wait1() { asm volatile("cp.async.wait_group 1;" ::: "memory"); }
DINLINE void cp_wait2() { asm volatile("cp.async.wait_group 2;" ::: "memory"); }

DINLINE void split2(float a, float b, __nv_bfloat162& h, __nv_bfloat162& l) {
    h = __floats2bfloat162_rn(a, b);
    l = __floats2bfloat162_rn(a - __low2float(h), b - __high2float(h));
}

DINLINE void split2h(float a, float b, __half2& h, __half2& l) {
    h = __floats2half2_rn(a, b);
    l = __floats2half2_rn(a - __low2float(h), b - __high2float(h));
}

// ======================= scratch (no allocs) =======================
__device__ __align__(16) __nv_bfloat16 g_e128h[1024 * 128];
__device__ __align__(16) __nv_bfloat16 g_e128l[1024 * 128];
__device__ __align__(16) __nv_bfloat16 g_e256h[1024 * 256];
__device__ __align__(16) __nv_bfloat16 g_e256l[1024 * 256];
__device__ __align__(16) __nv_bfloat16 g_e512h[1024 * 512];
__device__ __align__(16) __nv_bfloat16 g_e512l[1024 * 512];
__device__ __align__(16) __half g_e1024h[1024 * 1024];   // fp16 split (for AB)
__device__ __align__(16) __half g_e1024l[1024 * 1024];
__device__ __align__(16) __nv_bfloat16 g_r1wh[256 * 128];
__device__ __align__(16) __nv_bfloat16 g_r1wl[256 * 128];
__device__ __align__(16) __nv_bfloat16 g_r2wh[512 * 256];
__device__ __align__(16) __nv_bfloat16 g_r2wl[512 * 256];
__device__ __align__(16) __nv_bfloat16 g_r3wh[1024 * 512];
__device__ __align__(16) __nv_bfloat16 g_r3wl[1024 * 512];
__device__ __align__(16) __half g_wab[1024 * 1024];      // w1 combined, single fp16
__device__ __align__(16) float g_AB[1024 * 1024];   // cols [0,512)=A, [512,1024)=B
__device__ __align__(16) float g_m[16 * 512];

// ======================= fused prep: weight splits + w1 fp16 + embedding =======================
DINLINE void split_store4(const float4* __restrict__ src, __nv_bfloat162* __restrict__ h,
                          __nv_bfloat162* __restrict__ l, int i) {
    float4 v = src[i];
    __nv_bfloat162 h0, l0, h1, l1;
    split2(v.x, v.y, h0, l0);
    split2(v.z, v.w, h1, l1);
    h[2 * i] = h0; h[2 * i + 1] = h1;
    l[2 * i] = l0; l[2 * i + 1] = l1;
}

// blocks: [0,32) r1w, [32,160) r2w, [160,672) r3w, [672,1696) w1 gather (fp16), [1696,2208) embed
__global__ __launch_bounds__(256) void prep_kernel(
    const float* __restrict__ r1w, __nv_bfloat162* __restrict__ r1h, __nv_bfloat162* __restrict__ r1l,
    const float* __restrict__ r2w, __nv_bfloat162* __restrict__ r2h, __nv_bfloat162* __restrict__ r2l,
    const float* __restrict__ r3w, __nv_bfloat162* __restrict__ r3h, __nv_bfloat162* __restrict__ r3l,
    const float* __restrict__ w1, __half2* __restrict__ wab,
    const float* __restrict__ x,
    const float* __restrict__ e1w, const float* __restrict__ e1b,
    const float* __restrict__ e2w, const float* __restrict__ e2b,
    __nv_bfloat16* __restrict__ oh, __nv_bfloat16* __restrict__ ol) {
    int b = blockIdx.x, tid = threadIdx.x;
    if (b < 32) {
        split_store4((const float4*)r1w, r1h, r1l, b * 256 + tid);
    } else if (b < 160) {
        split_store4((const float4*)r2w, r2h, r2l, (b - 32) * 256 + tid);
    } else if (b < 672) {
        split_store4((const float4*)r3w, r3h, r3l, (b - 160) * 256 + tid);
    } else if (b < 1696) {
        int i = (b - 672) * 256 + tid;      // over 1024*256 float4 groups
        int n = i >> 8, kq = i & 255;
        const float* src = (n < 512) ? (w1 + (size_t)n * 2048 + kq * 4)
                                     : (w1 + (size_t)(n - 512) * 2048 + 1024 + kq * 4);
        float4 v = *(const float4*)src;
        size_t o = (size_t)n * 512 + kq * 2;   // half2 units
        wab[o] = __floats2half2_rn(v.x, v.y);
        wab[o + 1] = __floats2half2_rn(v.z, v.w);
    } else {
        __shared__ float xr[2][16];
        int rb = tid >> 7;
        int t = tid & 127;
        int row = (b - 1696) * 2 + rb;
        if (t < 16) xr[rb][t] = x[row * 16 + t];
        __syncthreads();
        float s1 = e1b[t];
#pragma unroll
        for (int c = 0; c < 3; c++) s1 = fmaf(xr[rb][c], e1w[t * 3 + c], s1);
        float s2 = e2b[t];
#pragma unroll
        for (int c = 0; c < 13; c++) s2 = fmaf(xr[rb][3 + c], e2w[t * 13 + c], s2);
        float v = fmaxf(s1, 0.f) + fmaxf(s2, 0.f);
        __nv_bfloat16 h = __float2bfloat16(v);
        oh[row * 128 + t] = h;
        ol[row * 128 + t] = __float2bfloat16(v - __bfloat162float(h));
    }
}

// ======================= warp-mma split-bf16 GEMM (R8 config) =======================
// OUTM==1: bias+relu -> split bf16.  OUTM==2: bias+relu -> split fp16 (for AB consumer).
static constexpr int GSTRIDE = 144;   // 64 x 2B = 128B + 16B pad
static constexpr int NSTAGE = 4;

template <int BM> struct GemmCfg {
    static constexpr int T = BM * 2;
    static constexpr int OFF_AL = BM * GSTRIDE;
    static constexpr int OFF_WH = 2 * BM * GSTRIDE;
    static constexpr int OFF_WL = OFF_WH + 64 * GSTRIDE;
    static constexpr int STAGE = OFF_WL + 64 * GSTRIDE;
    static constexpr int SMEM = NSTAGE * STAGE;
};

template <int BM, int OUTM>
__global__ __launch_bounds__(BM * 2) void mma_gemm(
    const __nv_bfloat16* __restrict__ Ah, const __nv_bfloat16* __restrict__ Al,
    const __nv_bfloat16* __restrict__ Wh, const __nv_bfloat16* __restrict__ Wl,
    const float* __restrict__ bias, int K,
    __nv_bfloat16* __restrict__ outH, __nv_bfloat16* __restrict__ outL,
    __half* __restrict__ outHh, __half* __restrict__ outLh, int ldo) {
    using C = GemmCfg<BM>;
    extern __shared__ char smc[];
    uint32_t sbase = smem_u32(smc);

    int tid = threadIdx.x, lane = tid & 31, wid = tid >> 5;
    int mw = wid >> 1, nw = wid & 1;
    int m0 = blockIdx.y * BM, n0 = blockIdx.x * 64;

    float acc[2][4][4] = {};

    uint32_t aoff = (lane & 15) * GSTRIDE + ((lane >> 4) << 4);
    uint32_t boff = ((((lane >> 4) << 3) + (lane & 7)) * GSTRIDE) + (((lane >> 3) & 1) << 4);
    uint32_t aBase0 = sbase + mw * 32 * GSTRIDE + aoff;
    uint32_t bBase0 = sbase + C::OFF_WH + nw * 32 * GSTRIDE + boff;

    constexpr int RPI = C::T / 8;
    int lrow = tid >> 3, lu = tid & 7;
    uint32_t sAh = sbase, sAl = sbase + C::OFF_AL, sWh = sbase + C::OFF_WH, sWl = sbase + C::OFF_WL;

    int nc = K >> 6;

    auto load_stage = [&](int c) {
        int k0 = c << 6;
        uint32_t so = (uint32_t)(c & (NSTAGE - 1)) * C::STAGE;
#pragma unroll
        for (int q = 0; q < BM / RPI; ++q) {
            int row = lrow + q * RPI;
            size_t go = (size_t)(m0 + row) * K + k0 + lu * 8;
            uint32_t sro = row * GSTRIDE + lu * 16 + so;
            cp16(sAh + sro, Ah + go);
            cp16(sAl + sro, Al + go);
        }
#pragma unroll
        for (int q = 0; q < 64 / RPI; ++q) {
            int row = lrow + q * RPI;
            size_t go = (size_t)(n0 + row) * K + k0 + lu * 8;
            uint32_t sro = row * GSTRIDE + lu * 16 + so;
            cp16(sWh + sro, Wh + go);
            cp16(sWl + sro, Wl + go);
        }
        cp_commit();
    };

    int issued = (nc < 3) ? nc : 3;
    for (int c = 0; c < issued; ++c) load_stage(c);

    for (int c = 0; c < nc; ++c) {
        int w = issued - c - 1;
        if (w <= 0) cp_wait0();
        else if (w == 1) cp_wait1();
        else cp_wait2();
        __syncthreads();
        if (issued < nc) { load_stage(issued); ++issued; }

        uint32_t so = (uint32_t)(c & (NSTAGE - 1)) * C::STAGE;
        uint32_t aBase = aBase0 + so, bBase = bBase0 + so;
#pragma unroll
        for (int kk = 0; kk < 4; ++kk) {
            uint32_t ah[2][4], al[2][4], bh[4][2], bl[4][2];
#pragma unroll
            for (int mi = 0; mi < 2; ++mi) {
                ldsm_x4(aBase + mi * (16 * GSTRIDE) + kk * 32, ah[mi]);
                ldsm_x4(aBase + C::OFF_AL + mi * (16 * GSTRIDE) + kk * 32, al[mi]);
            }
#pragma unroll
            for (int p = 0; p < 2; ++p) {
                uint32_t r4[4];
                ldsm_x4(bBase + p * (16 * GSTRIDE) + kk * 32, r4);
                bh[2 * p][0] = r4[0]; bh[2 * p][1] = r4[1];
                bh[2 * p + 1][0] = r4[2]; bh[2 * p + 1][1] = r4[3];
                ldsm_x4(bBase + (C::OFF_WL - C::OFF_WH) + p * (16 * GSTRIDE) + kk * 32, r4);
                bl[2 * p][0] = r4[0]; bl[2 * p][1] = r4[1];
                bl[2 * p + 1][0] = r4[2]; bl[2 * p + 1][1] = r4[3];
            }
#pragma unroll
            for (int mi = 0; mi < 2; ++mi)
#pragma unroll
                for (int ni = 0; ni < 4; ++ni)
                    mma16816(acc[mi][ni], ah[mi], bh[ni]);
#pragma unroll
            for (int mi = 0; mi < 2; ++mi)
#pragma unroll
                for (int ni = 0; ni < 4; ++ni)
                    mma16816(acc[mi][ni], ah[mi], bl[ni]);
#pragma unroll
            for (int mi = 0; mi < 2; ++mi)
#pragma unroll
                for (int ni = 0; ni < 4; ++ni)
                    mma16816(acc[mi][ni], al[mi], bh[ni]);
        }
    }

    int r = lane >> 2, c2 = (lane & 3) * 2;
    int warpM = m0 + mw * 32, warpN = n0 + nw * 32;
#pragma unroll
    for (int mi = 0; mi < 2; ++mi)
#pragma unroll
        for (int ni = 0; ni < 4; ++ni) {
            int n = warpN + ni * 8 + c2;
#pragma unroll
            for (int h = 0; h < 2; ++h) {
                int m = warpM + mi * 16 + r + h * 8;
                float2 bb = *(const float2*)(bias + n);
                float v0 = fmaxf(acc[mi][ni][h * 2 + 0] + bb.x, 0.f);
                float v1 = fmaxf(acc[mi][ni][h * 2 + 1] + bb.y, 0.f);
                if (OUTM == 1) {
                    __nv_bfloat162 hh, ll;
                    split2(v0, v1, hh, ll);
                    *(__nv_bfloat162*)(outH + (size_t)m * ldo + n) = hh;
                    *(__nv_bfloat162*)(outL + (size_t)m * ldo + n) = ll;
                } else {
                    __half2 hh, ll;
                    split2h(v0, v1, hh, ll);
                    *(__half2*)(outHh + (size_t)m * ldo + n) = hh;
                    *(__half2*)(outLh + (size_t)m * ldo + n) = ll;
                }
            }
        }
}

// ======================= AB GEMM: fp16 2-term (A split hi/lo, W single fp16) ==========
// C[m][n] = sum_k (Ah+Al)[m][k] * W[n][k].  128x64 tile, 256 thr, 4-stage, term-major.
static constexpr int H_OFF_AL = 128 * GSTRIDE;              // 18432
static constexpr int H_OFF_W = 2 * H_OFF_AL;                // 36864
static constexpr int H_STAGE = H_OFF_W + 64 * GSTRIDE;      // 46080
static constexpr int H_SMEM = NSTAGE * H_STAGE;             // 184320

__global__ __launch_bounds__(256) void hgemm_ab(
    const __half* __restrict__ Ah, const __half* __restrict__ Al,
    const __half* __restrict__ W, int K,
    float* __restrict__ outF, int ldo) {
    extern __shared__ char smc[];
    uint32_t sbase = smem_u32(smc);

    int tid = threadIdx.x, lane = tid & 31, wid = tid >> 5;
    int mw = wid >> 1, nw = wid & 1;
    int m0 = blockIdx.y * 128, n0 = blockIdx.x * 64;

    float acc[2][4][4] = {};

    uint32_t aoff = (lane & 15) * GSTRIDE + ((lane >> 4) << 4);
    uint32_t boff = ((((lane >> 4) << 3) + (lane & 7)) * GSTRIDE) + (((lane >> 3) & 1) << 4);
    uint32_t aBase0 = sbase + mw * 32 * GSTRIDE + aoff;
    uint32_t bBase0 = sbase + H_OFF_W + nw * 32 * GSTRIDE + boff;

    int lrow = tid >> 3, lu = tid & 7;      // 32 rows per q-iter
    uint32_t sAh = sbase, sAl = sbase + H_OFF_AL, sW = sbase + H_OFF_W;

    int nc = K >> 6;
    auto load_stage = [&](int c) {
        int k0 = c << 6;
        uint32_t so = (uint32_t)(c & (NSTAGE - 1)) * H_STAGE;
#pragma unroll
        for (int q = 0; q < 4; ++q) {       // A: 128 rows
            int row = lrow + q * 32;
            size_t go = (size_t)(m0 + row) * K + k0 + lu * 8;
            uint32_t sro = row * GSTRIDE + lu * 16 + so;
            cp16(sAh + sro, Ah + go);
            cp16(sAl + sro, Al + go);
        }
#pragma unroll
        for (int q = 0; q < 2; ++q) {       // W: 64 rows
            int row = lrow + q * 32;
            size_t go = (size_t)(n0 + row) * K + k0 + lu * 8;
            uint32_t sro = row * GSTRIDE + lu * 16 + so;
            cp16(sW + sro, W + go);
        }
        cp_commit();
    };

    int issued = (nc < 3) ? nc : 3;
    for (int c = 0; c < issued; ++c) load_stage(c);

    for (int c = 0; c < nc; ++c) {
        int w = issued - c - 1;
        if (w <= 0) cp_wait0();
        else if (w == 1) cp_wait1();
        else cp_wait2();
        __syncthreads();
        if (issued < nc) { load_stage(issued); ++issued; }

        uint32_t so = (uint32_t)(c & (NSTAGE - 1)) * H_STAGE;
        uint32_t aBase = aBase0 + so, bBase = bBase0 + so;
#pragma unroll
        for (int kk = 0; kk < 4; ++kk) {
            uint32_t ah[2][4], al[2][4], bw[4][2];
#pragma unroll
            for (int mi = 0; mi < 2; ++mi) {
                ldsm_x4(aBase + mi * (16 * GSTRIDE) + kk * 32, ah[mi]);
                ldsm_x4(aBase + H_OFF_AL + mi * (16 * GSTRIDE) + kk * 32, al[mi]);
            }
#pragma unroll
            for (int p = 0; p < 2; ++p) {
                uint32_t r4[4];
                ldsm_x4(bBase + p * (16 * GSTRIDE) + kk * 32, r4);
                bw[2 * p][0] = r4[0]; bw[2 * p][1] = r4[1];
                bw[2 * p + 1][0] = r4[2]; bw[2 * p + 1][1] = r4[3];
            }
            // term-major: h-term for all 8 accs, then l-term
#pragma unroll
            for (int mi = 0; mi < 2; ++mi)
#pragma unroll
                for (int ni = 0; ni < 4; ++ni)
                    mma16816h(acc[mi][ni], ah[mi], bw[ni]);
#pragma unroll
            for (int mi = 0; mi < 2; ++mi)
#pragma unroll
                for (int ni = 0; ni < 4; ++ni)
                    mma16816h(acc[mi][ni], al[mi], bw[ni]);
        }
    }

    int r = lane >> 2, c2 = (lane & 3) * 2;
    int warpM = m0 + mw * 32, warpN = n0 + nw * 32;
#pragma unroll
    for (int mi = 0; mi < 2; ++mi)
#pragma unroll
        for (int ni = 0; ni < 4; ++ni) {
            int n = warpN + ni * 8 + c2;
#pragma unroll
            for (int h = 0; h < 2; ++h) {
                int m = warpM + mi * 16 + r + h * 8;
                *(float2*)(outF + (size_t)m * ldo + n) =
                    make_float2(acc[mi][ni][h * 2 + 0], acc[mi][ni][h * 2 + 1]);
            }
        }
}

// ======================= pairwise relu outer-sum mean =======================
__global__ __launch_bounds__(256) void pairwise_kernel(const float* __restrict__ AB,
                                                       const float* __restrict__ b1,
                                                       float* __restrict__ mout) {
    __shared__ float As[64][64];
    __shared__ float Bs[64][64];
    __shared__ float part[4][64];
    int t = threadIdx.x;
    int chunk = blockIdx.x;
    int b = blockIdx.y;
    int c0 = chunk * 64;
    const float* base = AB + (size_t)b * 64 * 1024;

#pragma unroll
    for (int q = 0; q < 4; q++) {
        int idx = t + q * 256;
        int row = idx >> 4;
        int seg = idx & 15;
        float4 va = *(const float4*)(base + row * 1024 + c0 + seg * 4);
        float4 vb = *(const float4*)(base + row * 1024 + 512 + c0 + seg * 4);
        *(float4*)&As[row][seg * 4] = va;
        *(float4*)&Bs[row][seg * 4] = vb;
    }
    __syncthreads();

    int c = t & 63;
    int ig = t >> 6;
    float bias = b1[c0 + c];
    float acc = 0.f;
    for (int i = ig * 16; i < ig * 16 + 16; i++) {
        float bb = Bs[i][c] + bias;
#pragma unroll
        for (int j = 0; j < 64; j++)
            acc += fmaxf(As[j][c] + bb, 0.f);
    }
    part[ig][c] = acc;
    __syncthreads();
    if (t < 64) {
        float s = part[0][t] + part[1][t] + part[2][t] + part[3][t];
        mout[b * 512 + c0 + t] = s * (1.0f / 4096.0f);
    }
}

// ======================= final 512 -> 2048 =======================
__global__ __launch_bounds__(256) void final_kernel(const float* __restrict__ m,
                                                    const float* __restrict__ w2,
                                                    const float* __restrict__ b2,
                                                    float* __restrict__ out) {
    __shared__ float sm[16 * 512];
    int t = threadIdx.x;
    for (int i = t; i < 16 * 512; i += 256) sm[i] = m[i];
    __syncthreads();

    int warp = t >> 5, lane = t & 31;
    int o = blockIdx.x * 8 + warp;
    float acc[16];
#pragma unroll
    for (int b = 0; b < 16; b++) acc[b] = 0.f;
    const float* wrow = w2 + (size_t)o * 512;
#pragma unroll
    for (int kc = 0; kc < 16; kc++) {
        int k = kc * 32 + lane;
        float wv = wrow[k];
#pragma unroll
        for (int b = 0; b < 16; b++) acc[b] = fmaf(wv, sm[b * 512 + k], acc[b]);
    }
#pragma unroll
    for (int b = 0; b < 16; b++) {
        float v = acc[b];
#pragma unroll
        for (int s = 16; s > 0; s >>= 1) v += __shfl_xor_sync(0xffffffffu, v, s);
        if (lane == 0) out[b * 2048 + o] = v + b2[o];
    }
}

// ======================= launch =======================
extern "C" void kernel_launch(void* const* d_in, const int* in_sizes, int n_in,
                              void* d_out, int out_size) {
    (void)in_sizes; (void)n_in; (void)out_size;
    const float* x   = (const float*)d_in[0];
    const float* e1w = (const float*)d_in[1];
    const float* e1b = (const float*)d_in[2];
    const float* e2w = (const float*)d_in[3];
    const float* e2b = (const float*)d_in[4];
    const float* r1w = (const float*)d_in[5];
    const float* r1b = (const float*)d_in[6];
    const float* r2w = (const float*)d_in[7];
    const float* r2b = (const float*)d_in[8];
    const float* r3w = (const float*)d_in[9];
    const float* r3b = (const float*)d_in[10];
    const float* w1  = (const float*)d_in[11];
    const float* b1  = (const float*)d_in[12];
    const float* w2  = (const float*)d_in[13];
    const float* b2  = (const float*)d_in[14];
    float* out = (float*)d_out;

    __nv_bfloat16 *e128h, *e128l, *e256h, *e256l, *e512h, *e512l;
    __nv_bfloat16 *r1wh, *r1wl, *r2wh, *r2wl, *r3wh, *r3wl;
    __half *e1024h, *e1024l, *wab;
    float *AB, *mbuf;
    cudaGetSymbolAddress((void**)&e128h, g_e128h);
    cudaGetSymbolAddress((void**)&e128l, g_e128l);
    cudaGetSymbolAddress((void**)&e256h, g_e256h);
    cudaGetSymbolAddress((void**)&e256l, g_e256l);
    cudaGetSymbolAddress((void**)&e512h, g_e512h);
    cudaGetSymbolAddress((void**)&e512l, g_e512l);
    cudaGetSymbolAddress((void**)&e1024h, g_e1024h);
    cudaGetSymbolAddress((void**)&e1024l, g_e1024l);
    cudaGetSymbolAddress((void**)&r1wh, g_r1wh);
    cudaGetSymbolAddress((void**)&r1wl, g_r1wl);
    cudaGetSymbolAddress((void**)&r2wh, g_r2wh);
    cudaGetSymbolAddress((void**)&r2wl, g_r2wl);
    cudaGetSymbolAddress((void**)&r3wh, g_r3wh);
    cudaGetSymbolAddress((void**)&r3wl, g_r3wl);
    cudaGetSymbolAddress((void**)&wab, g_wab);
    cudaGetSymbolAddress((void**)&AB, g_AB);
    cudaGetSymbolAddress((void**)&mbuf, g_m);

    cudaFuncSetAttribute(mma_gemm<64, 1>, cudaFuncAttributeMaxDynamicSharedMemorySize, GemmCfg<64>::SMEM);
    cudaFuncSetAttribute(mma_gemm<128, 2>, cudaFuncAttributeMaxDynamicSharedMemorySize, GemmCfg<128>::SMEM);
    cudaFuncSetAttribute(hgemm_ab, cudaFuncAttributeMaxDynamicSharedMemorySize, H_SMEM);

    // fused prep: weight splits + w1 fp16 + embedding (one launch)
    prep_kernel<<<2208, 256>>>(r1w, (__nv_bfloat162*)r1wh, (__nv_bfloat162*)r1wl,
                               r2w, (__nv_bfloat162*)r2wh, (__nv_bfloat162*)r2wl,
                               r3w, (__nv_bfloat162*)r3wh, (__nv_bfloat162*)r3wl,
                               w1, (__half2*)wab,
                               x, e1w, e1b, e2w, e2b, e128h, e128l);

    // r1: 128 -> 256 (bias+relu, split bf16), BM=64 -> 64 CTAs
    mma_gemm<64, 1><<<dim3(4, 16), 128, GemmCfg<64>::SMEM>>>(
        e128h, e128l, r1wh, r1wl, r1b, 128, e256h, e256l, nullptr, nullptr, 256);
    // r2: 256 -> 512, BM=64 -> 128 CTAs
    mma_gemm<64, 1><<<dim3(8, 16), 128, GemmCfg<64>::SMEM>>>(
        e256h, e256l, r2wh, r2wl, r2b, 256, e512h, e512l, nullptr, nullptr, 512);
    // r3: 512 -> 1024, BM=128 -> 128 CTAs, fp16-split output
    mma_gemm<128, 2><<<dim3(16, 8), 256, GemmCfg<128>::SMEM>>>(
        e512h, e512l, r3wh, r3wl, r3b, 512, nullptr, nullptr, e1024h, e1024l, 1024);
    // A|B fused: 1024 -> 1024 fp16 2-term (raw fp32 out), 128 CTAs
    hgemm_ab<<<dim3(16, 8), 256, H_SMEM>>>(e1024h, e1024l, wab, 1024, AB, 1024);

    // pairwise mean -> m[16][512]
    pairwise_kernel<<<dim3(8, 16), 256>>>(AB, b1, mbuf);

    // final 512 -> 2048
    final_kernel<<<2048 / 8, 256>>>(mbuf, w2, b2, out);
}

// round 14
// speedup vs baseline: 2.0560x; 1.0320x over previous
#include <cuda_runtime.h>
#include <cuda_bf16.h>
#include <cuda_fp16.h>
#include <stdint.h>

#define DINLINE __device__ __forceinline__

DINLINE uint32_t smem_u32(const void* p) {
    uint32_t a;
    asm("{ .reg .u64 t; cvta.to.shared.u64 t, %1; cvt.u32.u64 %0, t; }" : "=r"(a) : "l"(p));
    return a;
}

DINLINE void ldsm_x4(uint32_t addr, uint32_t* r) {
    asm volatile("ldmatrix.sync.aligned.m8n8.x4.shared.b16 {%0,%1,%2,%3}, [%4];"
                 : "=r"(r[0]), "=r"(r[1]), "=r"(r[2]), "=r"(r[3]) : "r"(addr));
}

DINLINE void mma16816(float* d, const uint32_t* a, const uint32_t* b) {
    asm volatile("mma.sync.aligned.m16n8k16.row.col.f32.bf16.bf16.f32 "
                 "{%0,%1,%2,%3}, {%4,%5,%6,%7}, {%8,%9}, {%0,%1,%2,%3};"
                 : "+f"(d[0]), "+f"(d[1]), "+f"(d[2]), "+f"(d[3])
                 : "r"(a[0]), "r"(a[1]), "r"(a[2]), "r"(a[3]), "r"(b[0]), "r"(b[1]));
}

DINLINE void mma16816h(float* d, const uint32_t* a, const uint32_t* b) {
    asm volatile("mma.sync.aligned.m16n8k16.row.col.f32.f16.f16.f32 "
                 "{%0,%1,%2,%3}, {%4,%5,%6,%7}, {%8,%9}, {%0,%1,%2,%3};"
                 : "+f"(d[0]), "+f"(d[1]), "+f"(d[2]), "+f"(d[3])
                 : "r"(a[0]), "r"(a[1]), "r"(a[2]), "r"(a[3]), "r"(b[0]), "r"(b[1]));
}

DINLINE void cp16(uint32_t saddr, const void* g) {
    asm volatile("cp.async.cg.shared.global [%0], [%1], 16;" :: "r"(saddr), "l"(g));
}
DINLINE void cp_commit() { asm volatile("cp.async.commit_group;" ::: "memory"); }
DINLINE void cp_wait0() { asm volatile("cp.async.wait_group 0;" ::: "memory"); }
DINLINE void cp_wait1() { asm volatile("cp.async.wait_group 1;" ::: "memory"); }
DINLINE void cp_wait2() { asm volatile("cp.async.wait_group 2;" ::: "memory"); }

DINLINE void split2(float a, float b, __nv_bfloat162& h, __nv_bfloat162& l) {
    h = __floats2bfloat162_rn(a, b);
    l = __floats2bfloat162_rn(a - __low2float(h), b - __high2float(h));
}

DINLINE void split2h(float a, float b, __half2& h, __half2& l) {
    h = __floats2half2_rn(a, b);
    l = __floats2half2_rn(a - __low2float(h), b - __high2float(h));
}

// ======================= scratch (no allocs) =======================
__device__ __align__(16) __nv_bfloat16 g_e128h[1024 * 128];
__device__ __align__(16) __nv_bfloat16 g_e128l[1024 * 128];
__device__ __align__(16) __nv_bfloat16 g_e256h[1024 * 256];
__device__ __align__(16) __nv_bfloat16 g_e256l[1024 * 256];
__device__ __align__(16) __half g_e512h[1024 * 512];     // fp16 split (for r3)
__device__ __align__(16) __half g_e512l[1024 * 512];
__device__ __align__(16) __half g_e1024h[1024 * 1024];   // fp16 split (for AB)
__device__ __align__(16) __half g_e1024l[1024 * 1024];
__device__ __align__(16) __nv_bfloat16 g_r1wh[256 * 128];
__device__ __align__(16) __nv_bfloat16 g_r1wl[256 * 128];
__device__ __align__(16) __nv_bfloat16 g_r2wh[512 * 256];
__device__ __align__(16) __nv_bfloat16 g_r2wl[512 * 256];
__device__ __align__(16) __half g_r3w[1024 * 512];       // r3w single fp16
__device__ __align__(16) __half g_wab[1024 * 1024];      // w1 combined, single fp16
__device__ __align__(16) float g_AB[1024 * 1024];        // cols [0,512)=A, [512,1024)=B
__device__ __align__(16) float g_m[16 * 512];

// ======================= fused prep =======================
DINLINE void split_store4(const float4* __restrict__ src, __nv_bfloat162* __restrict__ h,
                          __nv_bfloat162* __restrict__ l, int i) {
    float4 v = src[i];
    __nv_bfloat162 h0, l0, h1, l1;
    split2(v.x, v.y, h0, l0);
    split2(v.z, v.w, h1, l1);
    h[2 * i] = h0; h[2 * i + 1] = h1;
    l[2 * i] = l0; l[2 * i + 1] = l1;
}

// blocks: [0,32) r1w split, [32,160) r2w split, [160,672) r3w fp16,
//         [672,1696) w1 gather fp16, [1696,2208) embed
__global__ __launch_bounds__(256) void prep_kernel(
    const float* __restrict__ r1w, __nv_bfloat162* __restrict__ r1h, __nv_bfloat162* __restrict__ r1l,
    const float* __restrict__ r2w, __nv_bfloat162* __restrict__ r2h, __nv_bfloat162* __restrict__ r2l,
    const float* __restrict__ r3w, __half2* __restrict__ r3o,
    const float* __restrict__ w1, __half2* __restrict__ wab,
    const float* __restrict__ x,
    const float* __restrict__ e1w, const float* __restrict__ e1b,
    const float* __restrict__ e2w, const float* __restrict__ e2b,
    __nv_bfloat16* __restrict__ oh, __nv_bfloat16* __restrict__ ol) {
    int b = blockIdx.x, tid = threadIdx.x;
    if (b < 32) {
        split_store4((const float4*)r1w, r1h, r1l, b * 256 + tid);
    } else if (b < 160) {
        split_store4((const float4*)r2w, r2h, r2l, (b - 32) * 256 + tid);
    } else if (b < 672) {
        int i = (b - 160) * 256 + tid;      // over 1024*512/4 float4 groups
        float4 v = ((const float4*)r3w)[i];
        r3o[2 * i] = __floats2half2_rn(v.x, v.y);
        r3o[2 * i + 1] = __floats2half2_rn(v.z, v.w);
    } else if (b < 1696) {
        int i = (b - 672) * 256 + tid;      // over 1024*256 float4 groups
        int n = i >> 8, kq = i & 255;
        const float* src = (n < 512) ? (w1 + (size_t)n * 2048 + kq * 4)
                                     : (w1 + (size_t)(n - 512) * 2048 + 1024 + kq * 4);
        float4 v = *(const float4*)src;
        size_t o = (size_t)n * 512 + kq * 2;   // half2 units
        wab[o] = __floats2half2_rn(v.x, v.y);
        wab[o + 1] = __floats2half2_rn(v.z, v.w);
    } else {
        __shared__ float xr[2][16];
        int rb = tid >> 7;
        int t = tid & 127;
        int row = (b - 1696) * 2 + rb;
        if (t < 16) xr[rb][t] = x[row * 16 + t];
        __syncthreads();
        float s1 = e1b[t];
#pragma unroll
        for (int c = 0; c < 3; c++) s1 = fmaf(xr[rb][c], e1w[t * 3 + c], s1);
        float s2 = e2b[t];
#pragma unroll
        for (int c = 0; c < 13; c++) s2 = fmaf(xr[rb][3 + c], e2w[t * 13 + c], s2);
        float v = fmaxf(s1, 0.f) + fmaxf(s2, 0.f);
        __nv_bfloat16 h = __float2bfloat16(v);
        oh[row * 128 + t] = h;
        ol[row * 128 + t] = __float2bfloat16(v - __bfloat162float(h));
    }
}

// ======================= bf16x3 GEMM (r1/r2), R8 config =======================
// OUTM==1: bias+relu -> split bf16.  OUTM==2: bias+relu -> split fp16.
static constexpr int GSTRIDE = 144;   // 64 x 2B = 128B + 16B pad
static constexpr int NSTAGE = 4;

template <int BM> struct GemmCfg {
    static constexpr int T = BM * 2;
    static constexpr int OFF_AL = BM * GSTRIDE;
    static constexpr int OFF_WH = 2 * BM * GSTRIDE;
    static constexpr int OFF_WL = OFF_WH + 64 * GSTRIDE;
    static constexpr int STAGE = OFF_WL + 64 * GSTRIDE;
    static constexpr int SMEM = NSTAGE * STAGE;
};

template <int BM, int OUTM>
__global__ __launch_bounds__(BM * 2) void mma_gemm(
    const __nv_bfloat16* __restrict__ Ah, const __nv_bfloat16* __restrict__ Al,
    const __nv_bfloat16* __restrict__ Wh, const __nv_bfloat16* __restrict__ Wl,
    const float* __restrict__ bias, int K,
    __nv_bfloat16* __restrict__ outH, __nv_bfloat16* __restrict__ outL,
    __half* __restrict__ outHh, __half* __restrict__ outLh, int ldo) {
    using C = GemmCfg<BM>;
    extern __shared__ char smc[];
    uint32_t sbase = smem_u32(smc);

    int tid = threadIdx.x, lane = tid & 31, wid = tid >> 5;
    int mw = wid >> 1, nw = wid & 1;
    int m0 = blockIdx.y * BM, n0 = blockIdx.x * 64;

    float acc[2][4][4] = {};

    uint32_t aoff = (lane & 15) * GSTRIDE + ((lane >> 4) << 4);
    uint32_t boff = ((((lane >> 4) << 3) + (lane & 7)) * GSTRIDE) + (((lane >> 3) & 1) << 4);
    uint32_t aBase0 = sbase + mw * 32 * GSTRIDE + aoff;
    uint32_t bBase0 = sbase + C::OFF_WH + nw * 32 * GSTRIDE + boff;

    constexpr int RPI = C::T / 8;
    int lrow = tid >> 3, lu = tid & 7;
    uint32_t sAh = sbase, sAl = sbase + C::OFF_AL, sWh = sbase + C::OFF_WH, sWl = sbase + C::OFF_WL;

    int nc = K >> 6;

    auto load_stage = [&](int c) {
        int k0 = c << 6;
        uint32_t so = (uint32_t)(c & (NSTAGE - 1)) * C::STAGE;
#pragma unroll
        for (int q = 0; q < BM / RPI; ++q) {
            int row = lrow + q * RPI;
            size_t go = (size_t)(m0 + row) * K + k0 + lu * 8;
            uint32_t sro = row * GSTRIDE + lu * 16 + so;
            cp16(sAh + sro, Ah + go);
            cp16(sAl + sro, Al + go);
        }
#pragma unroll
        for (int q = 0; q < 64 / RPI; ++q) {
            int row = lrow + q * RPI;
            size_t go = (size_t)(n0 + row) * K + k0 + lu * 8;
            uint32_t sro = row * GSTRIDE + lu * 16 + so;
            cp16(sWh + sro, Wh + go);
            cp16(sWl + sro, Wl + go);
        }
        cp_commit();
    };

    int issued = (nc < 3) ? nc : 3;
    for (int c = 0; c < issued; ++c) load_stage(c);

    for (int c = 0; c < nc; ++c) {
        int w = issued - c - 1;
        if (w <= 0) cp_wait0();
        else if (w == 1) cp_wait1();
        else cp_wait2();
        __syncthreads();
        if (issued < nc) { load_stage(issued); ++issued; }

        uint32_t so = (uint32_t)(c & (NSTAGE - 1)) * C::STAGE;
        uint32_t aBase = aBase0 + so, bBase = bBase0 + so;
#pragma unroll
        for (int kk = 0; kk < 4; ++kk) {
            uint32_t ah[2][4], al[2][4], bh[4][2], bl[4][2];
#pragma unroll
            for (int mi = 0; mi < 2; ++mi) {
                ldsm_x4(aBase + mi * (16 * GSTRIDE) + kk * 32, ah[mi]);
                ldsm_x4(aBase + C::OFF_AL + mi * (16 * GSTRIDE) + kk * 32, al[mi]);
            }
#pragma unroll
            for (int p = 0; p < 2; ++p) {
                uint32_t r4[4];
                ldsm_x4(bBase + p * (16 * GSTRIDE) + kk * 32, r4);
                bh[2 * p][0] = r4[0]; bh[2 * p][1] = r4[1];
                bh[2 * p + 1][0] = r4[2]; bh[2 * p + 1][1] = r4[3];
                ldsm_x4(bBase + (C::OFF_WL - C::OFF_WH) + p * (16 * GSTRIDE) + kk * 32, r4);
                bl[2 * p][0] = r4[0]; bl[2 * p][1] = r4[1];
                bl[2 * p + 1][0] = r4[2]; bl[2 * p + 1][1] = r4[3];
            }
#pragma unroll
            for (int mi = 0; mi < 2; ++mi)
#pragma unroll
                for (int ni = 0; ni < 4; ++ni)
                    mma16816(acc[mi][ni], ah[mi], bh[ni]);
#pragma unroll
            for (int mi = 0; mi < 2; ++mi)
#pragma unroll
                for (int ni = 0; ni < 4; ++ni)
                    mma16816(acc[mi][ni], ah[mi], bl[ni]);
#pragma unroll
            for (int mi = 0; mi < 2; ++mi)
#pragma unroll
                for (int ni = 0; ni < 4; ++ni)
                    mma16816(acc[mi][ni], al[mi], bh[ni]);
        }
    }

    int r = lane >> 2, c2 = (lane & 3) * 2;
    int warpM = m0 + mw * 32, warpN = n0 + nw * 32;
#pragma unroll
    for (int mi = 0; mi < 2; ++mi)
#pragma unroll
        for (int ni = 0; ni < 4; ++ni) {
            int n = warpN + ni * 8 + c2;
#pragma unroll
            for (int h = 0; h < 2; ++h) {
                int m = warpM + mi * 16 + r + h * 8;
                float2 bb = *(const float2*)(bias + n);
                float v0 = fmaxf(acc[mi][ni][h * 2 + 0] + bb.x, 0.f);
                float v1 = fmaxf(acc[mi][ni][h * 2 + 1] + bb.y, 0.f);
                if (OUTM == 1) {
                    __nv_bfloat162 hh, ll;
                    split2(v0, v1, hh, ll);
                    *(__nv_bfloat162*)(outH + (size_t)m * ldo + n) = hh;
                    *(__nv_bfloat162*)(outL + (size_t)m * ldo + n) = ll;
                } else {
                    __half2 hh, ll;
                    split2h(v0, v1, hh, ll);
                    *(__half2*)(outHh + (size_t)m * ldo + n) = hh;
                    *(__half2*)(outLh + (size_t)m * ldo + n) = ll;
                }
            }
        }
}

// ======================= fp16 2-term GEMM (r3 and AB) ==========
// C[m][n] = sum_k (Ah+Al)[m][k] * W[n][k].  128x64 tile, 256 thr, 4-stage, term-major.
// OUTM==0: raw fp32.  OUTM==1: bias+relu -> fp16 split.
static constexpr int H_OFF_AL = 128 * GSTRIDE;              // 18432
static constexpr int H_OFF_W = 2 * H_OFF_AL;                // 36864
static constexpr int H_STAGE = H_OFF_W + 64 * GSTRIDE;      // 46080
static constexpr int H_SMEM = NSTAGE * H_STAGE;             // 184320

template <int OUTM>
__global__ __launch_bounds__(256) void hgemm(
    const __half* __restrict__ Ah, const __half* __restrict__ Al,
    const __half* __restrict__ W, const float* __restrict__ bias, int K,
    float* __restrict__ outF, __half* __restrict__ outHh, __half* __restrict__ outLh,
    int ldo) {
    extern __shared__ char smc[];
    uint32_t sbase = smem_u32(smc);

    int tid = threadIdx.x, lane = tid & 31, wid = tid >> 5;
    int mw = wid >> 1, nw = wid & 1;
    int m0 = blockIdx.y * 128, n0 = blockIdx.x * 64;

    float acc[2][4][4] = {};

    uint32_t aoff = (lane & 15) * GSTRIDE + ((lane >> 4) << 4);
    uint32_t boff = ((((lane >> 4) << 3) + (lane & 7)) * GSTRIDE) + (((lane >> 3) & 1) << 4);
    uint32_t aBase0 = sbase + mw * 32 * GSTRIDE + aoff;
    uint32_t bBase0 = sbase + H_OFF_W + nw * 32 * GSTRIDE + boff;

    int lrow = tid >> 3, lu = tid & 7;      // 32 rows per q-iter
    uint32_t sAh = sbase, sAl = sbase + H_OFF_AL, sW = sbase + H_OFF_W;

    int nc = K >> 6;
    auto load_stage = [&](int c) {
        int k0 = c << 6;
        uint32_t so = (uint32_t)(c & (NSTAGE - 1)) * H_STAGE;
#pragma unroll
        for (int q = 0; q < 4; ++q) {       // A: 128 rows
            int row = lrow + q * 32;
            size_t go = (size_t)(m0 + row) * K + k0 + lu * 8;
            uint32_t sro = row * GSTRIDE + lu * 16 + so;
            cp16(sAh + sro, Ah + go);
            cp16(sAl + sro, Al + go);
        }
#pragma unroll
        for (int q = 0; q < 2; ++q) {       // W: 64 rows
            int row = lrow + q * 32;
            size_t go = (size_t)(n0 + row) * K + k0 + lu * 8;
            uint32_t sro = row * GSTRIDE + lu * 16 + so;
            cp16(sW + sro, W + go);
        }
        cp_commit();
    };

    int issued = (nc < 3) ? nc : 3;
    for (int c = 0; c < issued; ++c) load_stage(c);

    for (int c = 0; c < nc; ++c) {
        int w = issued - c - 1;
        if (w <= 0) cp_wait0();
        else if (w == 1) cp_wait1();
        else cp_wait2();
        __syncthreads();
        if (issued < nc) { load_stage(issued); ++issued; }

        uint32_t so = (uint32_t)(c & (NSTAGE - 1)) * H_STAGE;
        uint32_t aBase = aBase0 + so, bBase = bBase0 + so;
#pragma unroll
        for (int kk = 0; kk < 4; ++kk) {
            uint32_t ah[2][4], al[2][4], bw[4][2];
#pragma unroll
            for (int mi = 0; mi < 2; ++mi) {
                ldsm_x4(aBase + mi * (16 * GSTRIDE) + kk * 32, ah[mi]);
                ldsm_x4(aBase + H_OFF_AL + mi * (16 * GSTRIDE) + kk * 32, al[mi]);
            }
#pragma unroll
            for (int p = 0; p < 2; ++p) {
                uint32_t r4[4];
                ldsm_x4(bBase + p * (16 * GSTRIDE) + kk * 32, r4);
                bw[2 * p][0] = r4[0]; bw[2 * p][1] = r4[1];
                bw[2 * p + 1][0] = r4[2]; bw[2 * p + 1][1] = r4[3];
            }
            // term-major: h-term for all 8 accs, then l-term
#pragma unroll
            for (int mi = 0; mi < 2; ++mi)
#pragma unroll
                for (int ni = 0; ni < 4; ++ni)
                    mma16816h(acc[mi][ni], ah[mi], bw[ni]);
#pragma unroll
            for (int mi = 0; mi < 2; ++mi)
#pragma unroll
                for (int ni = 0; ni < 4; ++ni)
                    mma16816h(acc[mi][ni], al[mi], bw[ni]);
        }
    }

    int r = lane >> 2, c2 = (lane & 3) * 2;
    int warpM = m0 + mw * 32, warpN = n0 + nw * 32;
#pragma unroll
    for (int mi = 0; mi < 2; ++mi)
#pragma unroll
        for (int ni = 0; ni < 4; ++ni) {
            int n = warpN + ni * 8 + c2;
#pragma unroll
            for (int h = 0; h < 2; ++h) {
                int m = warpM + mi * 16 + r + h * 8;
                float v0 = acc[mi][ni][h * 2 + 0];
                float v1 = acc[mi][ni][h * 2 + 1];
                if (OUTM == 1) {
                    float2 bb = *(const float2*)(bias + n);
                    v0 = fmaxf(v0 + bb.x, 0.f);
                    v1 = fmaxf(v1 + bb.y, 0.f);
                    __half2 hh, ll;
                    split2h(v0, v1, hh, ll);
                    *(__half2*)(outHh + (size_t)m * ldo + n) = hh;
                    *(__half2*)(outLh + (size_t)m * ldo + n) = ll;
                } else {
                    *(float2*)(outF + (size_t)m * ldo + n) = make_float2(v0, v1);
                }
            }
        }
}

// ======================= pairwise relu outer-sum mean =======================
__global__ __launch_bounds__(256) void pairwise_kernel(const float* __restrict__ AB,
                                                       const float* __restrict__ b1,
                                                       float* __restrict__ mout) {
    __shared__ float As[64][64];
    __shared__ float Bs[64][64];
    __shared__ float part[4][64];
    int t = threadIdx.x;
    int chunk = blockIdx.x;
    int b = blockIdx.y;
    int c0 = chunk * 64;
    const float* base = AB + (size_t)b * 64 * 1024;

#pragma unroll
    for (int q = 0; q < 4; q++) {
        int idx = t + q * 256;
        int row = idx >> 4;
        int seg = idx & 15;
        float4 va = *(const float4*)(base + row * 1024 + c0 + seg * 4);
        float4 vb = *(const float4*)(base + row * 1024 + 512 + c0 + seg * 4);
        *(float4*)&As[row][seg * 4] = va;
        *(float4*)&Bs[row][seg * 4] = vb;
    }
    __syncthreads();

    int c = t & 63;
    int ig = t >> 6;
    float bias = b1[c0 + c];
    float acc = 0.f;
    for (int i = ig * 16; i < ig * 16 + 16; i++) {
        float bb = Bs[i][c] + bias;
#pragma unroll
        for (int j = 0; j < 64; j++)
            acc += fmaxf(As[j][c] + bb, 0.f);
    }
    part[ig][c] = acc;
    __syncthreads();
    if (t < 64) {
        float s = part[0][t] + part[1][t] + part[2][t] + part[3][t];
        mout[b * 512 + c0 + t] = s * (1.0f / 4096.0f);
    }
}

// ======================= final 512 -> 2048 =======================
__global__ __launch_bounds__(256) void final_kernel(const float* __restrict__ m,
                                                    const float* __restrict__ w2,
                                                    const float* __restrict__ b2,
                                                    float* __restrict__ out) {
    __shared__ float sm[16 * 512];
    int t = threadIdx.x;
    for (int i = t; i < 16 * 512; i += 256) sm[i] = m[i];
    __syncthreads();

    int warp = t >> 5, lane = t & 31;
    int o = blockIdx.x * 8 + warp;
    float acc[16];
#pragma unroll
    for (int b = 0; b < 16; b++) acc[b] = 0.f;
    const float* wrow = w2 + (size_t)o * 512;
#pragma unroll
    for (int kc = 0; kc < 16; kc++) {
        int k = kc * 32 + lane;
        float wv = wrow[k];
#pragma unroll
        for (int b = 0; b < 16; b++) acc[b] = fmaf(wv, sm[b * 512 + k], acc[b]);
    }
#pragma unroll
    for (int b = 0; b < 16; b++) {
        float v = acc[b];
#pragma unroll
        for (int s = 16; s > 0; s >>= 1) v += __shfl_xor_sync(0xffffffffu, v, s);
        if (lane == 0) out[b * 2048 + o] = v + b2[o];
    }
}

// ======================= launch =======================
extern "C" void kernel_launch(void* const* d_in, const int* in_sizes, int n_in,
                              void* d_out, int out_size) {
    (void)in_sizes; (void)n_in; (void)out_size;
    const float* x   = (const float*)d_in[0];
    const float* e1w = (const float*)d_in[1];
    const float* e1b = (const float*)d_in[2];
    const float* e2w = (const float*)d_in[3];
    const float* e2b = (const float*)d_in[4];
    const float* r1w = (const float*)d_in[5];
    const float* r1b = (const float*)d_in[6];
    const float* r2w = (const float*)d_in[7];
    const float* r2b = (const float*)d_in[8];
    const float* r3w = (const float*)d_in[9];
    const float* r3b = (const float*)d_in[10];
    const float* w1  = (const float*)d_in[11];
    const float* b1  = (const float*)d_in[12];
    const float* w2  = (const float*)d_in[13];
    const float* b2  = (const float*)d_in[14];
    float* out = (float*)d_out;

    __nv_bfloat16 *e128h, *e128l, *e256h, *e256l;
    __nv_bfloat16 *r1wh, *r1wl, *r2wh, *r2wl;
    __half *e512h, *e512l, *e1024h, *e1024l, *r3wq, *wab;
    float *AB, *mbuf;
    cudaGetSymbolAddress((void**)&e128h, g_e128h);
    cudaGetSymbolAddress((void**)&e128l, g_e128l);
    cudaGetSymbolAddress((void**)&e256h, g_e256h);
    cudaGetSymbolAddress((void**)&e256l, g_e256l);
    cudaGetSymbolAddress((void**)&e512h, g_e512h);
    cudaGetSymbolAddress((void**)&e512l, g_e512l);
    cudaGetSymbolAddress((void**)&e1024h, g_e1024h);
    cudaGetSymbolAddress((void**)&e1024l, g_e1024l);
    cudaGetSymbolAddress((void**)&r1wh, g_r1wh);
    cudaGetSymbolAddress((void**)&r1wl, g_r1wl);
    cudaGetSymbolAddress((void**)&r2wh, g_r2wh);
    cudaGetSymbolAddress((void**)&r2wl, g_r2wl);
    cudaGetSymbolAddress((void**)&r3wq, g_r3w);
    cudaGetSymbolAddress((void**)&wab, g_wab);
    cudaGetSymbolAddress((void**)&AB, g_AB);
    cudaGetSymbolAddress((void**)&mbuf, g_m);

    cudaFuncSetAttribute(mma_gemm<64, 1>, cudaFuncAttributeMaxDynamicSharedMemorySize, GemmCfg<64>::SMEM);
    cudaFuncSetAttribute(mma_gemm<64, 2>, cudaFuncAttributeMaxDynamicSharedMemorySize, GemmCfg<64>::SMEM);
    cudaFuncSetAttribute(hgemm<0>, cudaFuncAttributeMaxDynamicSharedMemorySize, H_SMEM);
    cudaFuncSetAttribute(hgemm<1>, cudaFuncAttributeMaxDynamicSharedMemorySize, H_SMEM);

    // fused prep (one launch)
    prep_kernel<<<2208, 256>>>(r1w, (__nv_bfloat162*)r1wh, (__nv_bfloat162*)r1wl,
                               r2w, (__nv_bfloat162*)r2wh, (__nv_bfloat162*)r2wl,
                               r3w, (__half2*)r3wq,
                               w1, (__half2*)wab,
                               x, e1w, e1b, e2w, e2b, e128h, e128l);

    // r1: 128 -> 256 bf16x3 (split bf16 out), 64 CTAs
    mma_gemm<64, 1><<<dim3(4, 16), 128, GemmCfg<64>::SMEM>>>(
        e128h, e128l, r1wh, r1wl, r1b, 128, e256h, e256l, nullptr, nullptr, 256);
    // r2: 256 -> 512 bf16x3 (split fp16 out), 128 CTAs
    mma_gemm<64, 2><<<dim3(8, 16), 128, GemmCfg<64>::SMEM>>>(
        e256h, e256l, r2wh, r2wl, r2b, 256, nullptr, nullptr, e512h, e512l, 512);
    // r3: 512 -> 1024 fp16 2-term (bias+relu -> split fp16), 128 CTAs
    hgemm<1><<<dim3(16, 8), 256, H_SMEM>>>(
        e512h, e512l, r3wq, r3b, 512, nullptr, e1024h, e1024l, 1024);
    // A|B fused: 1024 -> 1024 fp16 2-term (raw fp32 out), 128 CTAs
    hgemm<0><<<dim3(16, 8), 256, H_SMEM>>>(
        e1024h, e1024l, wab, nullptr, 1024, AB, nullptr, nullptr, 1024);

    // pairwise mean -> m[16][512]
    pairwise_kernel<<<dim3(8, 16), 256>>>(AB, b1, mbuf);

    // final 512 -> 2048
    final_kernel<<<2048 / 8, 256>>>(mbuf, w2, b2, out);
}

// round 15
// speedup vs baseline: 2.5449x; 1.2378x over previous
#include <cuda_runtime.h>
#include <cuda_bf16.h>
#include <cuda_fp16.h>
#include <stdint.h>

#define DINLINE __device__ __forceinline__

DINLINE uint32_t smem_u32(const void* p) {
    uint32_t a;
    asm("{ .reg .u64 t; cvta.to.shared.u64 t, %1; cvt.u32.u64 %0, t; }" : "=r"(a) : "l"(p));
    return a;
}

DINLINE void ldsm_x4(uint32_t addr, uint32_t* r) {
    asm volatile("ldmatrix.sync.aligned.m8n8.x4.shared.b16 {%0,%1,%2,%3}, [%4];"
                 : "=r"(r[0]), "=r"(r[1]), "=r"(r[2]), "=r"(r[3]) : "r"(addr));
}

DINLINE void mma16816(float* d, const uint32_t* a, const uint32_t* b) {
    asm volatile("mma.sync.aligned.m16n8k16.row.col.f32.bf16.bf16.f32 "
                 "{%0,%1,%2,%3}, {%4,%5,%6,%7}, {%8,%9}, {%0,%1,%2,%3};"
                 : "+f"(d[0]), "+f"(d[1]), "+f"(d[2]), "+f"(d[3])
                 : "r"(a[0]), "r"(a[1]), "r"(a[2]), "r"(a[3]), "r"(b[0]), "r"(b[1]));
}

DINLINE void mma16816h(float* d, const uint32_t* a, const uint32_t* b) {
    asm volatile("mma.sync.aligned.m16n8k16.row.col.f32.f16.f16.f32 "
                 "{%0,%1,%2,%3}, {%4,%5,%6,%7}, {%8,%9}, {%0,%1,%2,%3};"
                 : "+f"(d[0]), "+f"(d[1]), "+f"(d[2]), "+f"(d[3])
                 : "r"(a[0]), "r"(a[1]), "r"(a[2]), "r"(a[3]), "r"(b[0]), "r"(b[1]));
}

DINLINE void cp16(uint32_t saddr, const void* g) {
    asm volatile("cp.async.cg.shared.global [%0], [%1], 16;" :: "r"(saddr), "l"(g));
}
DINLINE void cp_commit() { asm volatile("cp.async.commit_group;" ::: "memory"); }
DINLINE void cp_wait0() { asm volatile("cp.async.wait_group 0;" ::: "memory"); }
DINLINE void cp_wait1() { asm volatile("cp.async.wait_group 1;" ::: "memory"); }
DINLINE void cp_wait2() { asm volatile("cp.async.wait_group 2;" ::: "memory"); }

DINLINE void split2(float a, float b, __nv_bfloat162& h, __nv_bfloat162& l) {
    h = __floats2bfloat162_rn(a, b);
    l = __floats2bfloat162_rn(a - __low2float(h), b - __high2float(h));
}

// ======================= scratch (no allocs) =======================
__device__ __align__(16) __nv_bfloat16 g_e128h[1024 * 128];
__device__ __align__(16) __nv_bfloat16 g_e128l[1024 * 128];
__device__ __align__(16) __nv_bfloat16 g_e256h[1024 * 256];
__device__ __align__(16) __nv_bfloat16 g_e256l[1024 * 256];
__device__ __align__(16) __half g_e512[1024 * 512];      // single fp16 (for r3)
__device__ __align__(16) __half g_e1024[1024 * 1024];    // single fp16 (for AB)
__device__ __align__(16) __nv_bfloat16 g_r1wh[256 * 128];
__device__ __align__(16) __nv_bfloat16 g_r1wl[256 * 128];
__device__ __align__(16) __nv_bfloat16 g_r2wh[512 * 256];
__device__ __align__(16) __nv_bfloat16 g_r2wl[512 * 256];
__device__ __align__(16) __half g_r3w[1024 * 512];       // r3w single fp16
__device__ __align__(16) __half g_wab[1024 * 1024];      // w1 combined, single fp16
__device__ __align__(16) float g_AB[1024 * 1024];        // cols [0,512)=A, [512,1024)=B
__device__ __align__(16) float g_m[16 * 512];

// ======================= fused prep =======================
DINLINE void split_store4(const float4* __restrict__ src, __nv_bfloat162* __restrict__ h,
                          __nv_bfloat162* __restrict__ l, int i) {
    float4 v = src[i];
    __nv_bfloat162 h0, l0, h1, l1;
    split2(v.x, v.y, h0, l0);
    split2(v.z, v.w, h1, l1);
    h[2 * i] = h0; h[2 * i + 1] = h1;
    l[2 * i] = l0; l[2 * i + 1] = l1;
}

// blocks: [0,32) r1w split, [32,160) r2w split, [160,672) r3w fp16,
//         [672,1696) w1 gather fp16, [1696,2208) embed
__global__ __launch_bounds__(256) void prep_kernel(
    const float* __restrict__ r1w, __nv_bfloat162* __restrict__ r1h, __nv_bfloat162* __restrict__ r1l,
    const float* __restrict__ r2w, __nv_bfloat162* __restrict__ r2h, __nv_bfloat162* __restrict__ r2l,
    const float* __restrict__ r3w, __half2* __restrict__ r3o,
    const float* __restrict__ w1, __half2* __restrict__ wab,
    const float* __restrict__ x,
    const float* __restrict__ e1w, const float* __restrict__ e1b,
    const float* __restrict__ e2w, const float* __restrict__ e2b,
    __nv_bfloat16* __restrict__ oh, __nv_bfloat16* __restrict__ ol) {
    int b = blockIdx.x, tid = threadIdx.x;
    if (b < 32) {
        split_store4((const float4*)r1w, r1h, r1l, b * 256 + tid);
    } else if (b < 160) {
        split_store4((const float4*)r2w, r2h, r2l, (b - 32) * 256 + tid);
    } else if (b < 672) {
        int i = (b - 160) * 256 + tid;      // over 1024*512/4 float4 groups
        float4 v = ((const float4*)r3w)[i];
        r3o[2 * i] = __floats2half2_rn(v.x, v.y);
        r3o[2 * i + 1] = __floats2half2_rn(v.z, v.w);
    } else if (b < 1696) {
        int i = (b - 672) * 256 + tid;      // over 1024*256 float4 groups
        int n = i >> 8, kq = i & 255;
        const float* src = (n < 512) ? (w1 + (size_t)n * 2048 + kq * 4)
                                     : (w1 + (size_t)(n - 512) * 2048 + 1024 + kq * 4);
        float4 v = *(const float4*)src;
        size_t o = (size_t)n * 512 + kq * 2;   // half2 units
        wab[o] = __floats2half2_rn(v.x, v.y);
        wab[o + 1] = __floats2half2_rn(v.z, v.w);
    } else {
        __shared__ float xr[2][16];
        int rb = tid >> 7;
        int t = tid & 127;
        int row = (b - 1696) * 2 + rb;
        if (t < 16) xr[rb][t] = x[row * 16 + t];
        __syncthreads();
        float s1 = e1b[t];
#pragma unroll
        for (int c = 0; c < 3; c++) s1 = fmaf(xr[rb][c], e1w[t * 3 + c], s1);
        float s2 = e2b[t];
#pragma unroll
        for (int c = 0; c < 13; c++) s2 = fmaf(xr[rb][3 + c], e2w[t * 13 + c], s2);
        float v = fmaxf(s1, 0.f) + fmaxf(s2, 0.f);
        __nv_bfloat16 h = __float2bfloat16(v);
        oh[row * 128 + t] = h;
        ol[row * 128 + t] = __float2bfloat16(v - __bfloat162float(h));
    }
}

// ======================= bf16x3 GEMM (r1/r2), R8 config =======================
// OUTM==1: bias+relu -> split bf16.  OUTM==2: bias+relu -> single fp16.
static constexpr int GSTRIDE = 144;   // 64 x 2B = 128B + 16B pad
static constexpr int NSTAGE = 4;

template <int BM> struct GemmCfg {
    static constexpr int T = BM * 2;
    static constexpr int OFF_AL = BM * GSTRIDE;
    static constexpr int OFF_WH = 2 * BM * GSTRIDE;
    static constexpr int OFF_WL = OFF_WH + 64 * GSTRIDE;
    static constexpr int STAGE = OFF_WL + 64 * GSTRIDE;
    static constexpr int SMEM = NSTAGE * STAGE;
};

template <int BM, int OUTM>
__global__ __launch_bounds__(BM * 2) void mma_gemm(
    const __nv_bfloat16* __restrict__ Ah, const __nv_bfloat16* __restrict__ Al,
    const __nv_bfloat16* __restrict__ Wh, const __nv_bfloat16* __restrict__ Wl,
    const float* __restrict__ bias, int K,
    __nv_bfloat16* __restrict__ outH, __nv_bfloat16* __restrict__ outL,
    __half* __restrict__ outHh, int ldo) {
    using C = GemmCfg<BM>;
    extern __shared__ char smc[];
    uint32_t sbase = smem_u32(smc);

    int tid = threadIdx.x, lane = tid & 31, wid = tid >> 5;
    int mw = wid >> 1, nw = wid & 1;
    int m0 = blockIdx.y * BM, n0 = blockIdx.x * 64;

    float acc[2][4][4] = {};

    uint32_t aoff = (lane & 15) * GSTRIDE + ((lane >> 4) << 4);
    uint32_t boff = ((((lane >> 4) << 3) + (lane & 7)) * GSTRIDE) + (((lane >> 3) & 1) << 4);
    uint32_t aBase0 = sbase + mw * 32 * GSTRIDE + aoff;
    uint32_t bBase0 = sbase + C::OFF_WH + nw * 32 * GSTRIDE + boff;

    constexpr int RPI = C::T / 8;
    int lrow = tid >> 3, lu = tid & 7;
    uint32_t sAh = sbase, sAl = sbase + C::OFF_AL, sWh = sbase + C::OFF_WH, sWl = sbase + C::OFF_WL;

    int nc = K >> 6;

    auto load_stage = [&](int c) {
        int k0 = c << 6;
        uint32_t so = (uint32_t)(c & (NSTAGE - 1)) * C::STAGE;
#pragma unroll
        for (int q = 0; q < BM / RPI; ++q) {
            int row = lrow + q * RPI;
            size_t go = (size_t)(m0 + row) * K + k0 + lu * 8;
            uint32_t sro = row * GSTRIDE + lu * 16 + so;
            cp16(sAh + sro, Ah + go);
            cp16(sAl + sro, Al + go);
        }
#pragma unroll
        for (int q = 0; q < 64 / RPI; ++q) {
            int row = lrow + q * RPI;
            size_t go = (size_t)(n0 + row) * K + k0 + lu * 8;
            uint32_t sro = row * GSTRIDE + lu * 16 + so;
            cp16(sWh + sro, Wh + go);
            cp16(sWl + sro, Wl + go);
        }
        cp_commit();
    };

    int issued = (nc < 3) ? nc : 3;
    for (int c = 0; c < issued; ++c) load_stage(c);

    for (int c = 0; c < nc; ++c) {
        int w = issued - c - 1;
        if (w <= 0) cp_wait0();
        else if (w == 1) cp_wait1();
        else cp_wait2();
        __syncthreads();
        if (issued < nc) { load_stage(issued); ++issued; }

        uint32_t so = (uint32_t)(c & (NSTAGE - 1)) * C::STAGE;
        uint32_t aBase = aBase0 + so, bBase = bBase0 + so;
#pragma unroll
        for (int kk = 0; kk < 4; ++kk) {
            uint32_t ah[2][4], al[2][4], bh[4][2], bl[4][2];
#pragma unroll
            for (int mi = 0; mi < 2; ++mi) {
                ldsm_x4(aBase + mi * (16 * GSTRIDE) + kk * 32, ah[mi]);
                ldsm_x4(aBase + C::OFF_AL + mi * (16 * GSTRIDE) + kk * 32, al[mi]);
            }
#pragma unroll
            for (int p = 0; p < 2; ++p) {
                uint32_t r4[4];
                ldsm_x4(bBase + p * (16 * GSTRIDE) + kk * 32, r4);
                bh[2 * p][0] = r4[0]; bh[2 * p][1] = r4[1];
                bh[2 * p + 1][0] = r4[2]; bh[2 * p + 1][1] = r4[3];
                ldsm_x4(bBase + (C::OFF_WL - C::OFF_WH) + p * (16 * GSTRIDE) + kk * 32, r4);
                bl[2 * p][0] = r4[0]; bl[2 * p][1] = r4[1];
                bl[2 * p + 1][0] = r4[2]; bl[2 * p + 1][1] = r4[3];
            }
#pragma unroll
            for (int mi = 0; mi < 2; ++mi)
#pragma unroll
                for (int ni = 0; ni < 4; ++ni)
                    mma16816(acc[mi][ni], ah[mi], bh[ni]);
#pragma unroll
            for (int mi = 0; mi < 2; ++mi)
#pragma unroll
                for (int ni = 0; ni < 4; ++ni)
                    mma16816(acc[mi][ni], ah[mi], bl[ni]);
#pragma unroll
            for (int mi = 0; mi < 2; ++mi)
#pragma unroll
                for (int ni = 0; ni < 4; ++ni)
                    mma16816(acc[mi][ni], al[mi], bh[ni]);
        }
    }

    int r = lane >> 2, c2 = (lane & 3) * 2;
    int warpM = m0 + mw * 32, warpN = n0 + nw * 32;
#pragma unroll
    for (int mi = 0; mi < 2; ++mi)
#pragma unroll
        for (int ni = 0; ni < 4; ++ni) {
            int n = warpN + ni * 8 + c2;
#pragma unroll
            for (int h = 0; h < 2; ++h) {
                int m = warpM + mi * 16 + r + h * 8;
                float2 bb = *(const float2*)(bias + n);
                float v0 = fmaxf(acc[mi][ni][h * 2 + 0] + bb.x, 0.f);
                float v1 = fmaxf(acc[mi][ni][h * 2 + 1] + bb.y, 0.f);
                if (OUTM == 1) {
                    __nv_bfloat162 hh, ll;
                    split2(v0, v1, hh, ll);
                    *(__nv_bfloat162*)(outH + (size_t)m * ldo + n) = hh;
                    *(__nv_bfloat162*)(outL + (size_t)m * ldo + n) = ll;
                } else {
                    *(__half2*)(outHh + (size_t)m * ldo + n) = __floats2half2_rn(v0, v1);
                }
            }
        }
}

// ======================= fp16 1-term GEMM (r3 and AB) ==========
// C[m][n] = sum_k A[m][k] * W[n][k], both single fp16.  128x64 tile, 256 thr, 4-stage.
// OUTM==0: raw fp32.  OUTM==1: bias+relu -> single fp16.
static constexpr int H_OFF_W = 128 * GSTRIDE;               // 18432
static constexpr int H_STAGE = H_OFF_W + 64 * GSTRIDE;      // 27648
static constexpr int H_SMEM = NSTAGE * H_STAGE;             // 110592

template <int OUTM>
__global__ __launch_bounds__(256) void hgemm(
    const __half* __restrict__ A, const __half* __restrict__ W,
    const float* __restrict__ bias, int K,
    float* __restrict__ outF, __half* __restrict__ outHh, int ldo) {
    extern __shared__ char smc[];
    uint32_t sbase = smem_u32(smc);

    int tid = threadIdx.x, lane = tid & 31, wid = tid >> 5;
    int mw = wid >> 1, nw = wid & 1;
    int m0 = blockIdx.y * 128, n0 = blockIdx.x * 64;

    float acc[2][4][4] = {};

    uint32_t aoff = (lane & 15) * GSTRIDE + ((lane >> 4) << 4);
    uint32_t boff = ((((lane >> 4) << 3) + (lane & 7)) * GSTRIDE) + (((lane >> 3) & 1) << 4);
    uint32_t aBase0 = sbase + mw * 32 * GSTRIDE + aoff;
    uint32_t bBase0 = sbase + H_OFF_W + nw * 32 * GSTRIDE + boff;

    int lrow = tid >> 3, lu = tid & 7;      // 32 rows per q-iter
    uint32_t sA = sbase, sW = sbase + H_OFF_W;

    int nc = K >> 6;
    auto load_stage = [&](int c) {
        int k0 = c << 6;
        uint32_t so = (uint32_t)(c & (NSTAGE - 1)) * H_STAGE;
#pragma unroll
        for (int q = 0; q < 4; ++q) {       // A: 128 rows
            int row = lrow + q * 32;
            size_t go = (size_t)(m0 + row) * K + k0 + lu * 8;
            cp16(sA + row * GSTRIDE + lu * 16 + so, A + go);
        }
#pragma unroll
        for (int q = 0; q < 2; ++q) {       // W: 64 rows
            int row = lrow + q * 32;
            size_t go = (size_t)(n0 + row) * K + k0 + lu * 8;
            cp16(sW + row * GSTRIDE + lu * 16 + so, W + go);
        }
        cp_commit();
    };

    int issued = (nc < 3) ? nc : 3;
    for (int c = 0; c < issued; ++c) load_stage(c);

    for (int c = 0; c < nc; ++c) {
        int w = issued - c - 1;
        if (w <= 0) cp_wait0();
        else if (w == 1) cp_wait1();
        else cp_wait2();
        __syncthreads();
        if (issued < nc) { load_stage(issued); ++issued; }

        uint32_t so = (uint32_t)(c & (NSTAGE - 1)) * H_STAGE;
        uint32_t aBase = aBase0 + so, bBase = bBase0 + so;
#pragma unroll
        for (int kk = 0; kk < 4; ++kk) {
            uint32_t af[2][4], bw[4][2];
#pragma unroll
            for (int mi = 0; mi < 2; ++mi)
                ldsm_x4(aBase + mi * (16 * GSTRIDE) + kk * 32, af[mi]);
#pragma unroll
            for (int p = 0; p < 2; ++p) {
                uint32_t r4[4];
                ldsm_x4(bBase + p * (16 * GSTRIDE) + kk * 32, r4);
                bw[2 * p][0] = r4[0]; bw[2 * p][1] = r4[1];
                bw[2 * p + 1][0] = r4[2]; bw[2 * p + 1][1] = r4[3];
            }
#pragma unroll
            for (int mi = 0; mi < 2; ++mi)
#pragma unroll
                for (int ni = 0; ni < 4; ++ni)
                    mma16816h(acc[mi][ni], af[mi], bw[ni]);
        }
    }

    int r = lane >> 2, c2 = (lane & 3) * 2;
    int warpM = m0 + mw * 32, warpN = n0 + nw * 32;
#pragma unroll
    for (int mi = 0; mi < 2; ++mi)
#pragma unroll
        for (int ni = 0; ni < 4; ++ni) {
            int n = warpN + ni * 8 + c2;
#pragma unroll
            for (int h = 0; h < 2; ++h) {
                int m = warpM + mi * 16 + r + h * 8;
                float v0 = acc[mi][ni][h * 2 + 0];
                float v1 = acc[mi][ni][h * 2 + 1];
                if (OUTM == 1) {
                    float2 bb = *(const float2*)(bias + n);
                    v0 = fmaxf(v0 + bb.x, 0.f);
                    v1 = fmaxf(v1 + bb.y, 0.f);
                    *(__half2*)(outHh + (size_t)m * ldo + n) = __floats2half2_rn(v0, v1);
                } else {
                    *(float2*)(outF + (size_t)m * ldo + n) = make_float2(v0, v1);
                }
            }
        }
}

// ======================= pairwise relu outer-sum mean =======================
__global__ __launch_bounds__(256) void pairwise_kernel(const float* __restrict__ AB,
                                                       const float* __restrict__ b1,
                                                       float* __restrict__ mout) {
    __shared__ float As[64][64];
    __shared__ float Bs[64][64];
    __shared__ float part[4][64];
    int t = threadIdx.x;
    int chunk = blockIdx.x;
    int b = blockIdx.y;
    int c0 = chunk * 64;
    const float* base = AB + (size_t)b * 64 * 1024;

#pragma unroll
    for (int q = 0; q < 4; q++) {
        int idx = t + q * 256;
        int row = idx >> 4;
        int seg = idx & 15;
        float4 va = *(const float4*)(base + row * 1024 + c0 + seg * 4);
        float4 vb = *(const float4*)(base + row * 1024 + 512 + c0 + seg * 4);
        *(float4*)&As[row][seg * 4] = va;
        *(float4*)&Bs[row][seg * 4] = vb;
    }
    __syncthreads();

    int c = t & 63;
    int ig = t >> 6;
    float bias = b1[c0 + c];
    float acc = 0.f;
    for (int i = ig * 16; i < ig * 16 + 16; i++) {
        float bb = Bs[i][c] + bias;
#pragma unroll
        for (int j = 0; j < 64; j++)
            acc += fmaxf(As[j][c] + bb, 0.f);
    }
    part[ig][c] = acc;
    __syncthreads();
    if (t < 64) {
        float s = part[0][t] + part[1][t] + part[2][t] + part[3][t];
        mout[b * 512 + c0 + t] = s * (1.0f / 4096.0f);
    }
}

// ======================= final 512 -> 2048 =======================
__global__ __launch_bounds__(256) void final_kernel(const float* __restrict__ m,
                                                    const float* __restrict__ w2,
                                                    const float* __restrict__ b2,
                                                    float* __restrict__ out) {
    __shared__ float sm[16 * 512];
    int t = threadIdx.x;
    for (int i = t; i < 16 * 512; i += 256) sm[i] = m[i];
    __syncthreads();

    int warp = t >> 5, lane = t & 31;
    int o = blockIdx.x * 8 + warp;
    float acc[16];
#pragma unroll
    for (int b = 0; b < 16; b++) acc[b] = 0.f;
    const float* wrow = w2 + (size_t)o * 512;
#pragma unroll
    for (int kc = 0; kc < 16; kc++) {
        int k = kc * 32 + lane;
        float wv = wrow[k];
#pragma unroll
        for (int b = 0; b < 16; b++) acc[b] = fmaf(wv, sm[b * 512 + k], acc[b]);
    }
#pragma unroll
    for (int b = 0; b < 16; b++) {
        float v = acc[b];
#pragma unroll
        for (int s = 16; s > 0; s >>= 1) v += __shfl_xor_sync(0xffffffffu, v, s);
        if (lane == 0) out[b * 2048 + o] = v + b2[o];
    }
}

// ======================= launch =======================
extern "C" void kernel_launch(void* const* d_in, const int* in_sizes, int n_in,
                              void* d_out, int out_size) {
    (void)in_sizes; (void)n_in; (void)out_size;
    const float* x   = (const float*)d_in[0];
    const float* e1w = (const float*)d_in[1];
    const float* e1b = (const float*)d_in[2];
    const float* e2w = (const float*)d_in[3];
    const float* e2b = (const float*)d_in[4];
    const float* r1w = (const float*)d_in[5];
    const float* r1b = (const float*)d_in[6];
    const float* r2w = (const float*)d_in[7];
    const float* r2b = (const float*)d_in[8];
    const float* r3w = (const float*)d_in[9];
    const float* r3b = (const float*)d_in[10];
    const float* w1  = (const float*)d_in[11];
    const float* b1  = (const float*)d_in[12];
    const float* w2  = (const float*)d_in[13];
    const float* b2  = (const float*)d_in[14];
    float* out = (float*)d_out;

    __nv_bfloat16 *e128h, *e128l, *e256h, *e256l;
    __nv_bfloat16 *r1wh, *r1wl, *r2wh, *r2wl;
    __half *e512, *e1024, *r3wq, *wab;
    float *AB, *mbuf;
    cudaGetSymbolAddress((void**)&e128h, g_e128h);
    cudaGetSymbolAddress((void**)&e128l, g_e128l);
    cudaGetSymbolAddress((void**)&e256h, g_e256h);
    cudaGetSymbolAddress((void**)&e256l, g_e256l);
    cudaGetSymbolAddress((void**)&e512, g_e512);
    cudaGetSymbolAddress((void**)&e1024, g_e1024);
    cudaGetSymbolAddress((void**)&r1wh, g_r1wh);
    cudaGetSymbolAddress((void**)&r1wl, g_r1wl);
    cudaGetSymbolAddress((void**)&r2wh, g_r2wh);
    cudaGetSymbolAddress((void**)&r2wl, g_r2wl);
    cudaGetSymbolAddress((void**)&r3wq, g_r3w);
    cudaGetSymbolAddress((void**)&wab, g_wab);
    cudaGetSymbolAddress((void**)&AB, g_AB);
    cudaGetSymbolAddress((void**)&mbuf, g_m);

    cudaFuncSetAttribute(mma_gemm<64, 1>, cudaFuncAttributeMaxDynamicSharedMemorySize, GemmCfg<64>::SMEM);
    cudaFuncSetAttribute(mma_gemm<64, 2>, cudaFuncAttributeMaxDynamicSharedMemorySize, GemmCfg<64>::SMEM);
    cudaFuncSetAttribute(hgemm<0>, cudaFuncAttributeMaxDynamicSharedMemorySize, H_SMEM);
    cudaFuncSetAttribute(hgemm<1>, cudaFuncAttributeMaxDynamicSharedMemorySize, H_SMEM);

    // fused prep (one launch)
    prep_kernel<<<2208, 256>>>(r1w, (__nv_bfloat162*)r1wh, (__nv_bfloat162*)r1wl,
                               r2w, (__nv_bfloat162*)r2wh, (__nv_bfloat162*)r2wl,
                               r3w, (__half2*)r3wq,
                               w1, (__half2*)wab,
                               x, e1w, e1b, e2w, e2b, e128h, e128l);

    // r1: 128 -> 256 bf16x3 (split bf16 out), 64 CTAs
    mma_gemm<64, 1><<<dim3(4, 16), 128, GemmCfg<64>::SMEM>>>(
        e128h, e128l, r1wh, r1wl, r1b, 128, e256h, e256l, nullptr, 256);
    // r2: 256 -> 512 bf16x3 (single fp16 out), 128 CTAs
    mma_gemm<64, 2><<<dim3(8, 16), 128, GemmCfg<64>::SMEM>>>(
        e256h, e256l, r2wh, r2wl, r2b, 256, nullptr, nullptr, e512, 512);
    // r3: 512 -> 1024 fp16 1-term (bias+relu -> single fp16), 128 CTAs
    hgemm<1><<<dim3(16, 8), 256, H_SMEM>>>(e512, r3wq, r3b, 512, nullptr, e1024, 1024);
    // A|B fused: 1024 -> 1024 fp16 1-term (raw fp32 out), 128 CTAs
    hgemm<0><<<dim3(16, 8), 256, H_SMEM>>>(e1024, wab, nullptr, 1024, AB, nullptr, 1024);

    // pairwise mean -> m[16][512]
    pairwise_kernel<<<dim3(8, 16), 256>>>(AB, b1, mbuf);

    // final 512 -> 2048
    final_kernel<<<2048 / 8, 256>>>(mbuf, w2, b2, out);
}

// round 16
// speedup vs baseline: 2.6482x; 1.0406x over previous
#include <cuda_runtime.h>
#include <cuda_fp16.h>
#include <stdint.h>

#define DINLINE __device__ __forceinline__

DINLINE uint32_t smem_u32(const void* p) {
    uint32_t a;
    asm("{ .reg .u64 t; cvta.to.shared.u64 t, %1; cvt.u32.u64 %0, t; }" : "=r"(a) : "l"(p));
    return a;
}

DINLINE void ldsm_x4(uint32_t addr, uint32_t* r) {
    asm volatile("ldmatrix.sync.aligned.m8n8.x4.shared.b16 {%0,%1,%2,%3}, [%4];"
                 : "=r"(r[0]), "=r"(r[1]), "=r"(r[2]), "=r"(r[3]) : "r"(addr));
}

DINLINE void mma16816h(float* d, const uint32_t* a, const uint32_t* b) {
    asm volatile("mma.sync.aligned.m16n8k16.row.col.f32.f16.f16.f32 "
                 "{%0,%1,%2,%3}, {%4,%5,%6,%7}, {%8,%9}, {%0,%1,%2,%3};"
                 : "+f"(d[0]), "+f"(d[1]), "+f"(d[2]), "+f"(d[3])
                 : "r"(a[0]), "r"(a[1]), "r"(a[2]), "r"(a[3]), "r"(b[0]), "r"(b[1]));
}

DINLINE void cp16(uint32_t saddr, const void* g) {
    asm volatile("cp.async.cg.shared.global [%0], [%1], 16;" :: "r"(saddr), "l"(g));
}
DINLINE void cp_commit() { asm volatile("cp.async.commit_group;" ::: "memory"); }
DINLINE void cp_wait0() { asm volatile("cp.async.wait_group 0;" ::: "memory"); }
DINLINE void cp_wait1() { asm volatile("cp.async.wait_group 1;" ::: "memory"); }
DINLINE void cp_wait2() { asm volatile("cp.async.wait_group 2;" ::: "memory"); }

// ======================= scratch (no allocs) =======================
__device__ __align__(16) __half g_e128[1024 * 128];
__device__ __align__(16) __half g_e256[1024 * 256];
__device__ __align__(16) __half g_e512[1024 * 512];
__device__ __align__(16) __half g_e1024[1024 * 1024];
__device__ __align__(16) __half g_r1w[256 * 128];
__device__ __align__(16) __half g_r2w[512 * 256];
__device__ __align__(16) __half g_r3w[1024 * 512];
__device__ __align__(16) __half g_wab[1024 * 1024];   // w1 combined
__device__ __align__(16) __half g_ABh[1024 * 1024];   // cols [0,512)=A, [512,1024)=B
__device__ __align__(16) float g_m[16 * 512];

// ======================= fused prep: fp16 converts + embedding =======================
DINLINE void cvt_store4(const float4* __restrict__ src, __half2* __restrict__ dst, int i) {
    float4 v = src[i];
    dst[2 * i] = __floats2half2_rn(v.x, v.y);
    dst[2 * i + 1] = __floats2half2_rn(v.z, v.w);
}

// blocks: [0,32) r1w, [32,160) r2w, [160,672) r3w, [672,1696) w1 gather, [1696,2208) embed
__global__ __launch_bounds__(256) void prep_kernel(
    const float* __restrict__ r1w, __half2* __restrict__ r1o,
    const float* __restrict__ r2w, __half2* __restrict__ r2o,
    const float* __restrict__ r3w, __half2* __restrict__ r3o,
    const float* __restrict__ w1, __half2* __restrict__ wab,
    const float* __restrict__ x,
    const float* __restrict__ e1w, const float* __restrict__ e1b,
    const float* __restrict__ e2w, const float* __restrict__ e2b,
    __half* __restrict__ eo) {
    int b = blockIdx.x, tid = threadIdx.x;
    if (b < 32) {
        cvt_store4((const float4*)r1w, r1o, b * 256 + tid);
    } else if (b < 160) {
        cvt_store4((const float4*)r2w, r2o, (b - 32) * 256 + tid);
    } else if (b < 672) {
        cvt_store4((const float4*)r3w, r3o, (b - 160) * 256 + tid);
    } else if (b < 1696) {
        int i = (b - 672) * 256 + tid;      // over 1024*256 float4 groups
        int n = i >> 8, kq = i & 255;
        const float* src = (n < 512) ? (w1 + (size_t)n * 2048 + kq * 4)
                                     : (w1 + (size_t)(n - 512) * 2048 + 1024 + kq * 4);
        float4 v = *(const float4*)src;
        size_t o = (size_t)n * 512 + kq * 2;   // half2 units
        wab[o] = __floats2half2_rn(v.x, v.y);
        wab[o + 1] = __floats2half2_rn(v.z, v.w);
    } else {
        __shared__ float xr[2][16];
        int rb = tid >> 7;
        int t = tid & 127;
        int row = (b - 1696) * 2 + rb;
        if (t < 16) xr[rb][t] = x[row * 16 + t];
        __syncthreads();
        float s1 = e1b[t];
#pragma unroll
        for (int c = 0; c < 3; c++) s1 = fmaf(xr[rb][c], e1w[t * 3 + c], s1);
        float s2 = e2b[t];
#pragma unroll
        for (int c = 0; c < 13; c++) s2 = fmaf(xr[rb][3 + c], e2w[t * 13 + c], s2);
        float v = fmaxf(s1, 0.f) + fmaxf(s2, 0.f);
        eo[row * 128 + t] = __float2half(v);
    }
}

// ======================= fp16 1-term GEMM (all layers) ==========
// C[m][n] = sum_k A[m][k] * W[n][k].  BM x 64 tile, BM*2 threads, 4-stage cp.async.
// BM=64: 4 warps (2x2); BM=128: 8 warps (4x2). Warp tile 32x32.
// OUTM==0: raw fp16 out.  OUTM==1: bias+relu -> fp16 out.
static constexpr int GSTRIDE = 144;   // 64 halves = 128B + 16B pad
static constexpr int NSTAGE = 4;

template <int BM> struct HCfg {
    static constexpr int T = BM * 2;
    static constexpr int OFF_W = BM * GSTRIDE;
    static constexpr int STAGE = OFF_W + 64 * GSTRIDE;
    static constexpr int SMEM = NSTAGE * STAGE;
};

template <int BM, int OUTM>
__global__ __launch_bounds__(BM * 2) void hgemm(
    const __half* __restrict__ A, const __half* __restrict__ W,
    const float* __restrict__ bias, int K,
    __half* __restrict__ outH, int ldo) {
    using C = HCfg<BM>;
    extern __shared__ char smc[];
    uint32_t sbase = smem_u32(smc);

    int tid = threadIdx.x, lane = tid & 31, wid = tid >> 5;
    int mw = wid >> 1, nw = wid & 1;
    int m0 = blockIdx.y * BM, n0 = blockIdx.x * 64;

    float acc[2][4][4] = {};

    uint32_t aoff = (lane & 15) * GSTRIDE + ((lane >> 4) << 4);
    uint32_t boff = ((((lane >> 4) << 3) + (lane & 7)) * GSTRIDE) + (((lane >> 3) & 1) << 4);
    uint32_t aBase0 = sbase + mw * 32 * GSTRIDE + aoff;
    uint32_t bBase0 = sbase + C::OFF_W + nw * 32 * GSTRIDE + boff;

    constexpr int RPI = C::T / 8;
    int lrow = tid >> 3, lu = tid & 7;
    uint32_t sA = sbase, sW = sbase + C::OFF_W;

    int nc = K >> 6;
    auto load_stage = [&](int c) {
        int k0 = c << 6;
        uint32_t so = (uint32_t)(c & (NSTAGE - 1)) * C::STAGE;
#pragma unroll
        for (int q = 0; q < BM / RPI; ++q) {
            int row = lrow + q * RPI;
            size_t go = (size_t)(m0 + row) * K + k0 + lu * 8;
            cp16(sA + row * GSTRIDE + lu * 16 + so, A + go);
        }
#pragma unroll
        for (int q = 0; q < 64 / RPI; ++q) {
            int row = lrow + q * RPI;
            size_t go = (size_t)(n0 + row) * K + k0 + lu * 8;
            cp16(sW + row * GSTRIDE + lu * 16 + so, W + go);
        }
        cp_commit();
    };

    int issued = (nc < 3) ? nc : 3;
    for (int c = 0; c < issued; ++c) load_stage(c);

    for (int c = 0; c < nc; ++c) {
        int w = issued - c - 1;
        if (w <= 0) cp_wait0();
        else if (w == 1) cp_wait1();
        else cp_wait2();
        __syncthreads();
        if (issued < nc) { load_stage(issued); ++issued; }

        uint32_t so = (uint32_t)(c & (NSTAGE - 1)) * C::STAGE;
        uint32_t aBase = aBase0 + so, bBase = bBase0 + so;
#pragma unroll
        for (int kk = 0; kk < 4; ++kk) {
            uint32_t af[2][4], bw[4][2];
#pragma unroll
            for (int mi = 0; mi < 2; ++mi)
                ldsm_x4(aBase + mi * (16 * GSTRIDE) + kk * 32, af[mi]);
#pragma unroll
            for (int p = 0; p < 2; ++p) {
                uint32_t r4[4];
                ldsm_x4(bBase + p * (16 * GSTRIDE) + kk * 32, r4);
                bw[2 * p][0] = r4[0]; bw[2 * p][1] = r4[1];
                bw[2 * p + 1][0] = r4[2]; bw[2 * p + 1][1] = r4[3];
            }
#pragma unroll
            for (int mi = 0; mi < 2; ++mi)
#pragma unroll
                for (int ni = 0; ni < 4; ++ni)
                    mma16816h(acc[mi][ni], af[mi], bw[ni]);
        }
    }

    int r = lane >> 2, c2 = (lane & 3) * 2;
    int warpM = m0 + mw * 32, warpN = n0 + nw * 32;
#pragma unroll
    for (int mi = 0; mi < 2; ++mi)
#pragma unroll
        for (int ni = 0; ni < 4; ++ni) {
            int n = warpN + ni * 8 + c2;
#pragma unroll
            for (int h = 0; h < 2; ++h) {
                int m = warpM + mi * 16 + r + h * 8;
                float v0 = acc[mi][ni][h * 2 + 0];
                float v1 = acc[mi][ni][h * 2 + 1];
                if (OUTM == 1) {
                    float2 bb = *(const float2*)(bias + n);
                    v0 = fmaxf(v0 + bb.x, 0.f);
                    v1 = fmaxf(v1 + bb.y, 0.f);
                }
                *(__half2*)(outH + (size_t)m * ldo + n) = __floats2half2_rn(v0, v1);
            }
        }
}

// ======================= pairwise relu outer-sum mean (fp16 AB input) =======================
__global__ __launch_bounds__(256) void pairwise_kernel(const __half* __restrict__ ABh,
                                                       const float* __restrict__ b1,
                                                       float* __restrict__ mout) {
    __shared__ float As[64][64];
    __shared__ float Bs[64][64];
    __shared__ float part[4][64];
    int t = threadIdx.x;
    int chunk = blockIdx.x;
    int b = blockIdx.y;
    int c0 = chunk * 64;
    const __half* base = ABh + (size_t)b * 64 * 1024;

#pragma unroll
    for (int q = 0; q < 2; q++) {
        int idx = t + q * 256;            // 0..511
        int row = idx >> 3;               // 0..63
        int seg = idx & 7;                // 8 halves each
        const __half2* pa = (const __half2*)(base + (size_t)row * 1024 + c0 + seg * 8);
        const __half2* pb = (const __half2*)(base + (size_t)row * 1024 + 512 + c0 + seg * 8);
#pragma unroll
        for (int j = 0; j < 4; ++j) {
            float2 fa = __half22float2(pa[j]);
            float2 fb = __half22float2(pb[j]);
            As[row][seg * 8 + 2 * j + 0] = fa.x;
            As[row][seg * 8 + 2 * j + 1] = fa.y;
            Bs[row][seg * 8 + 2 * j + 0] = fb.x;
            Bs[row][seg * 8 + 2 * j + 1] = fb.y;
        }
    }
    __syncthreads();

    int c = t & 63;
    int ig = t >> 6;
    float bias = b1[c0 + c];
    float acc = 0.f;
    for (int i = ig * 16; i < ig * 16 + 16; i++) {
        float bb = Bs[i][c] + bias;
#pragma unroll
        for (int j = 0; j < 64; j++)
            acc += fmaxf(As[j][c] + bb, 0.f);
    }
    part[ig][c] = acc;
    __syncthreads();
    if (t < 64) {
        float s = part[0][t] + part[1][t] + part[2][t] + part[3][t];
        mout[b * 512 + c0 + t] = s * (1.0f / 4096.0f);
    }
}

// ======================= final 512 -> 2048 =======================
__global__ __launch_bounds__(256) void final_kernel(const float* __restrict__ m,
                                                    const float* __restrict__ w2,
                                                    const float* __restrict__ b2,
                                                    float* __restrict__ out) {
    __shared__ float sm[16 * 512];
    int t = threadIdx.x;
    for (int i = t; i < 16 * 512; i += 256) sm[i] = m[i];
    __syncthreads();

    int warp = t >> 5, lane = t & 31;
    int o = blockIdx.x * 8 + warp;
    float acc[16];
#pragma unroll
    for (int b = 0; b < 16; b++) acc[b] = 0.f;
    const float* wrow = w2 + (size_t)o * 512;
#pragma unroll
    for (int kc = 0; kc < 16; kc++) {
        int k = kc * 32 + lane;
        float wv = wrow[k];
#pragma unroll
        for (int b = 0; b < 16; b++) acc[b] = fmaf(wv, sm[b * 512 + k], acc[b]);
    }
#pragma unroll
    for (int b = 0; b < 16; b++) {
        float v = acc[b];
#pragma unroll
        for (int s = 16; s > 0; s >>= 1) v += __shfl_xor_sync(0xffffffffu, v, s);
        if (lane == 0) out[b * 2048 + o] = v + b2[o];
    }
}

// ======================= launch =======================
extern "C" void kernel_launch(void* const* d_in, const int* in_sizes, int n_in,
                              void* d_out, int out_size) {
    (void)in_sizes; (void)n_in; (void)out_size;
    const float* x   = (const float*)d_in[0];
    const float* e1w = (const float*)d_in[1];
    const float* e1b = (const float*)d_in[2];
    const float* e2w = (const float*)d_in[3];
    const float* e2b = (const float*)d_in[4];
    const float* r1w = (const float*)d_in[5];
    const float* r1b = (const float*)d_in[6];
    const float* r2w = (const float*)d_in[7];
    const float* r2b = (const float*)d_in[8];
    const float* r3w = (const float*)d_in[9];
    const float* r3b = (const float*)d_in[10];
    const float* w1  = (const float*)d_in[11];
    const float* b1  = (const float*)d_in[12];
    const float* w2  = (const float*)d_in[13];
    const float* b2  = (const float*)d_in[14];
    float* out = (float*)d_out;

    __half *e128, *e256, *e512, *e1024, *r1wq, *r2wq, *r3wq, *wab, *ABh;
    float *mbuf;
    cudaGetSymbolAddress((void**)&e128, g_e128);
    cudaGetSymbolAddress((void**)&e256, g_e256);
    cudaGetSymbolAddress((void**)&e512, g_e512);
    cudaGetSymbolAddress((void**)&e1024, g_e1024);
    cudaGetSymbolAddress((void**)&r1wq, g_r1w);
    cudaGetSymbolAddress((void**)&r2wq, g_r2w);
    cudaGetSymbolAddress((void**)&r3wq, g_r3w);
    cudaGetSymbolAddress((void**)&wab, g_wab);
    cudaGetSymbolAddress((void**)&ABh, g_ABh);
    cudaGetSymbolAddress((void**)&mbuf, g_m);

    cudaFuncSetAttribute(hgemm<64, 1>, cudaFuncAttributeMaxDynamicSharedMemorySize, HCfg<64>::SMEM);
    cudaFuncSetAttribute(hgemm<128, 1>, cudaFuncAttributeMaxDynamicSharedMemorySize, HCfg<128>::SMEM);
    cudaFuncSetAttribute(hgemm<128, 0>, cudaFuncAttributeMaxDynamicSharedMemorySize, HCfg<128>::SMEM);

    // fused prep: fp16 converts + embedding (one launch)
    prep_kernel<<<2208, 256>>>(r1w, (__half2*)r1wq, r2w, (__half2*)r2wq,
                               r3w, (__half2*)r3wq, w1, (__half2*)wab,
                               x, e1w, e1b, e2w, e2b, e128);

    // r1: 128 -> 256 (bias+relu), BM=64 -> 64 CTAs
    hgemm<64, 1><<<dim3(4, 16), 128, HCfg<64>::SMEM>>>(e128, r1wq, r1b, 128, e256, 256);
    // r2: 256 -> 512, BM=64 -> 128 CTAs
    hgemm<64, 1><<<dim3(8, 16), 128, HCfg<64>::SMEM>>>(e256, r2wq, r2b, 256, e512, 512);
    // r3: 512 -> 1024, BM=128 -> 128 CTAs
    hgemm<128, 1><<<dim3(16, 8), 256, HCfg<128>::SMEM>>>(e512, r3wq, r3b, 512, e1024, 1024);
    // A|B fused: 1024 -> 1024 (raw fp16 out), BM=128 -> 128 CTAs
    hgemm<128, 0><<<dim3(16, 8), 256, HCfg<128>::SMEM>>>(e1024, wab, nullptr, 1024, ABh, 1024);

    // pairwise mean -> m[16][512]
    pairwise_kernel<<<dim3(8, 16), 256>>>(ABh, b1, mbuf);

    // final 512 -> 2048
    final_kernel<<<2048 / 8, 256>>>(mbuf, w2, b2, out);
}

// round 17
// speedup vs baseline: 2.7473x; 1.0374x over previous
#include <cuda_runtime.h>
#include <cuda_fp16.h>
#include <stdint.h>

#define DINLINE __device__ __forceinline__

DINLINE uint32_t smem_u32(const void* p) {
    uint32_t a;
    asm("{ .reg .u64 t; cvta.to.shared.u64 t, %1; cvt.u32.u64 %0, t; }" : "=r"(a) : "l"(p));
    return a;
}

DINLINE void ldsm_x4(uint32_t addr, uint32_t* r) {
    asm volatile("ldmatrix.sync.aligned.m8n8.x4.shared.b16 {%0,%1,%2,%3}, [%4];"
                 : "=r"(r[0]), "=r"(r[1]), "=r"(r[2]), "=r"(r[3]) : "r"(addr));
}

DINLINE void mma16816h(float* d, const uint32_t* a, const uint32_t* b) {
    asm volatile("mma.sync.aligned.m16n8k16.row.col.f32.f16.f16.f32 "
                 "{%0,%1,%2,%3}, {%4,%5,%6,%7}, {%8,%9}, {%0,%1,%2,%3};"
                 : "+f"(d[0]), "+f"(d[1]), "+f"(d[2]), "+f"(d[3])
                 : "r"(a[0]), "r"(a[1]), "r"(a[2]), "r"(a[3]), "r"(b[0]), "r"(b[1]));
}

DINLINE void cp16(uint32_t saddr, const void* g) {
    asm volatile("cp.async.cg.shared.global [%0], [%1], 16;" :: "r"(saddr), "l"(g));
}
DINLINE void cp_commit() { asm volatile("cp.async.commit_group;" ::: "memory"); }
DINLINE void cp_wait0() { asm volatile("cp.async.wait_group 0;" ::: "memory"); }
DINLINE void cp_wait1() { asm volatile("cp.async.wait_group 1;" ::: "memory"); }
DINLINE void cp_wait2() { asm volatile("cp.async.wait_group 2;" ::: "memory"); }

// ======================= scratch (no allocs) =======================
__device__ __align__(16) __half g_e128[1024 * 128];
__device__ __align__(16) __half g_e256[1024 * 256];
__device__ __align__(16) __half g_e512[1024 * 512];
__device__ __align__(16) __half g_e1024[1024 * 1024];
__device__ __align__(16) __half g_r1w[256 * 128];
__device__ __align__(16) __half g_r2w[512 * 256];
__device__ __align__(16) __half g_r3w[1024 * 512];
__device__ __align__(16) __half g_wab[1024 * 1024];   // w1 combined
__device__ __align__(16) __half g_ABh[1024 * 1024];   // cols [0,512)=A, [512,1024)=B
__device__ __align__(16) float g_mp[4 * 16 * 512];    // pairwise partials (z-split)

// ======================= fused prep: fp16 converts + embedding =======================
DINLINE void cvt_store4(const float4* __restrict__ src, __half2* __restrict__ dst, int i) {
    float4 v = src[i];
    dst[2 * i] = __floats2half2_rn(v.x, v.y);
    dst[2 * i + 1] = __floats2half2_rn(v.z, v.w);
}

// blocks: [0,32) r1w, [32,160) r2w, [160,672) r3w, [672,1696) w1 gather, [1696,2208) embed
__global__ __launch_bounds__(256) void prep_kernel(
    const float* __restrict__ r1w, __half2* __restrict__ r1o,
    const float* __restrict__ r2w, __half2* __restrict__ r2o,
    const float* __restrict__ r3w, __half2* __restrict__ r3o,
    const float* __restrict__ w1, __half2* __restrict__ wab,
    const float* __restrict__ x,
    const float* __restrict__ e1w, const float* __restrict__ e1b,
    const float* __restrict__ e2w, const float* __restrict__ e2b,
    __half* __restrict__ eo) {
    int b = blockIdx.x, tid = threadIdx.x;
    if (b < 32) {
        cvt_store4((const float4*)r1w, r1o, b * 256 + tid);
    } else if (b < 160) {
        cvt_store4((const float4*)r2w, r2o, (b - 32) * 256 + tid);
    } else if (b < 672) {
        cvt_store4((const float4*)r3w, r3o, (b - 160) * 256 + tid);
    } else if (b < 1696) {
        int i = (b - 672) * 256 + tid;      // over 1024*256 float4 groups
        int n = i >> 8, kq = i & 255;
        const float* src = (n < 512) ? (w1 + (size_t)n * 2048 + kq * 4)
                                     : (w1 + (size_t)(n - 512) * 2048 + 1024 + kq * 4);
        float4 v = *(const float4*)src;
        size_t o = (size_t)n * 512 + kq * 2;   // half2 units
        wab[o] = __floats2half2_rn(v.x, v.y);
        wab[o + 1] = __floats2half2_rn(v.z, v.w);
    } else {
        __shared__ float xr[2][16];
        int rb = tid >> 7;
        int t = tid & 127;
        int row = (b - 1696) * 2 + rb;
        if (t < 16) xr[rb][t] = x[row * 16 + t];
        __syncthreads();
        float s1 = e1b[t];
#pragma unroll
        for (int c = 0; c < 3; c++) s1 = fmaf(xr[rb][c], e1w[t * 3 + c], s1);
        float s2 = e2b[t];
#pragma unroll
        for (int c = 0; c < 13; c++) s2 = fmaf(xr[rb][3 + c], e2w[t * 13 + c], s2);
        float v = fmaxf(s1, 0.f) + fmaxf(s2, 0.f);
        eo[row * 128 + t] = __float2half(v);
    }
}

// ======================= fp16 GEMM, small (r1/r2): 64x64 tile, K-chunk 64, 4-stage ===========
static constexpr int GSTRIDE = 144;   // 64 halves = 128B + 16B pad
static constexpr int S_OFF_W = 64 * GSTRIDE;
static constexpr int S_STAGE = S_OFF_W + 64 * GSTRIDE;   // 18432
static constexpr int S_SMEM = 4 * S_STAGE;               // 73728

__global__ __launch_bounds__(128) void hgemm_small(
    const __half* __restrict__ A, const __half* __restrict__ W,
    const float* __restrict__ bias, int K,
    __half* __restrict__ outH, int ldo) {
    extern __shared__ char smc[];
    uint32_t sbase = smem_u32(smc);

    int tid = threadIdx.x, lane = tid & 31, wid = tid >> 5;
    int mw = wid >> 1, nw = wid & 1;
    int m0 = blockIdx.y * 64, n0 = blockIdx.x * 64;

    float acc[2][4][4] = {};

    uint32_t aoff = (lane & 15) * GSTRIDE + ((lane >> 4) << 4);
    uint32_t boff = ((((lane >> 4) << 3) + (lane & 7)) * GSTRIDE) + (((lane >> 3) & 1) << 4);
    uint32_t aBase0 = sbase + mw * 32 * GSTRIDE + aoff;
    uint32_t bBase0 = sbase + S_OFF_W + nw * 32 * GSTRIDE + boff;

    int lrow = tid >> 3, lu = tid & 7;   // 16 rows per pass
    uint32_t sA = sbase, sW = sbase + S_OFF_W;

    int nc = K >> 6;
    auto load_stage = [&](int c) {
        int k0 = c << 6;
        uint32_t so = (uint32_t)(c & 3) * S_STAGE;
#pragma unroll
        for (int q = 0; q < 4; ++q) {
            int row = lrow + q * 16;
            size_t goA = (size_t)(m0 + row) * K + k0 + lu * 8;
            size_t goW = (size_t)(n0 + row) * K + k0 + lu * 8;
            uint32_t sro = row * GSTRIDE + lu * 16 + so;
            cp16(sA + sro, A + goA);
            cp16(sW + sro, W + goW);
        }
        cp_commit();
    };

    int issued = (nc < 3) ? nc : 3;
    for (int c = 0; c < issued; ++c) load_stage(c);

    for (int c = 0; c < nc; ++c) {
        int w = issued - c - 1;
        if (w <= 0) cp_wait0(); else if (w == 1) cp_wait1(); else cp_wait2();
        __syncthreads();
        if (issued < nc) { load_stage(issued); ++issued; }

        uint32_t so = (uint32_t)(c & 3) * S_STAGE;
        uint32_t aBase = aBase0 + so, bBase = bBase0 + so;
#pragma unroll
        for (int kk = 0; kk < 4; ++kk) {
            uint32_t af[2][4], bw[4][2];
#pragma unroll
            for (int mi = 0; mi < 2; ++mi)
                ldsm_x4(aBase + mi * (16 * GSTRIDE) + kk * 32, af[mi]);
#pragma unroll
            for (int p = 0; p < 2; ++p) {
                uint32_t r4[4];
                ldsm_x4(bBase + p * (16 * GSTRIDE) + kk * 32, r4);
                bw[2 * p][0] = r4[0]; bw[2 * p][1] = r4[1];
                bw[2 * p + 1][0] = r4[2]; bw[2 * p + 1][1] = r4[3];
            }
#pragma unroll
            for (int mi = 0; mi < 2; ++mi)
#pragma unroll
                for (int ni = 0; ni < 4; ++ni)
                    mma16816h(acc[mi][ni], af[mi], bw[ni]);
        }
    }

    int r = lane >> 2, c2 = (lane & 3) * 2;
    int warpM = m0 + mw * 32, warpN = n0 + nw * 32;
#pragma unroll
    for (int mi = 0; mi < 2; ++mi)
#pragma unroll
        for (int ni = 0; ni < 4; ++ni) {
            int n = warpN + ni * 8 + c2;
#pragma unroll
            for (int h = 0; h < 2; ++h) {
                int m = warpM + mi * 16 + r + h * 8;
                float2 bb = *(const float2*)(bias + n);
                float v0 = fmaxf(acc[mi][ni][h * 2 + 0] + bb.x, 0.f);
                float v1 = fmaxf(acc[mi][ni][h * 2 + 1] + bb.y, 0.f);
                *(__half2*)(outH + (size_t)m * ldo + n) = __floats2half2_rn(v0, v1);
            }
        }
}

// ======================= fp16 GEMM, big (r3/AB): 128x64 tile, K-chunk 128, 3-stage ===========
static constexpr int GSTR2 = 272;     // 128 halves = 256B + 16B pad
static constexpr int B_OFF_W = 128 * GSTR2;              // 34816
static constexpr int B_STAGE = B_OFF_W + 64 * GSTR2;     // 52224
static constexpr int B_SMEM = 3 * B_STAGE;               // 156672

template <int OUTM>
__global__ __launch_bounds__(256) void hgemm_big(
    const __half* __restrict__ A, const __half* __restrict__ W,
    const float* __restrict__ bias, int K,
    __half* __restrict__ outH, int ldo) {
    extern __shared__ char smc[];
    uint32_t sbase = smem_u32(smc);

    int tid = threadIdx.x, lane = tid & 31, wid = tid >> 5;
    int mw = wid >> 1, nw = wid & 1;
    int m0 = blockIdx.y * 128, n0 = blockIdx.x * 64;

    float acc[2][4][4] = {};

    uint32_t aoff = (lane & 15) * GSTR2 + ((lane >> 4) << 4);
    uint32_t boff = ((((lane >> 4) << 3) + (lane & 7)) * GSTR2) + (((lane >> 3) & 1) << 4);
    uint32_t aBase0 = sbase + mw * 32 * GSTR2 + aoff;
    uint32_t bBase0 = sbase + B_OFF_W + nw * 32 * GSTR2 + boff;

    int lrow = tid >> 4, lu = tid & 15;  // 16 rows per pass, 16 x 16B units per row
    uint32_t sA = sbase, sW = sbase + B_OFF_W;

    int nc = K >> 7;                      // K-chunk = 128
    auto load_stage = [&](int c) {        // stage c -> slot c % 3
        int k0 = c << 7;
        uint32_t slot = (uint32_t)(c % 3) * B_STAGE;
#pragma unroll
        for (int q = 0; q < 8; ++q) {     // A: 128 rows
            int row = lrow + q * 16;
            size_t go = (size_t)(m0 + row) * K + k0 + lu * 8;
            cp16(sA + row * GSTR2 + lu * 16 + slot, A + go);
        }
#pragma unroll
        for (int q = 0; q < 4; ++q) {     // W: 64 rows
            int row = lrow + q * 16;
            size_t go = (size_t)(n0 + row) * K + k0 + lu * 8;
            cp16(sW + row * GSTR2 + lu * 16 + slot, W + go);
        }
        cp_commit();
    };

    int issued = (nc < 2) ? nc : 2;
    for (int c = 0; c < issued; ++c) load_stage(c);

    for (int c = 0; c < nc; ++c) {
        int w = issued - c - 1;
        if (w <= 0) cp_wait0(); else cp_wait1();
        __syncthreads();
        if (issued < nc) { load_stage(issued); ++issued; }

        uint32_t slot = (uint32_t)(c % 3) * B_STAGE;
        uint32_t aBase = aBase0 + slot, bBase = bBase0 + slot;
#pragma unroll
        for (int kk = 0; kk < 8; ++kk) {
            uint32_t af[2][4], bw[4][2];
#pragma unroll
            for (int mi = 0; mi < 2; ++mi)
                ldsm_x4(aBase + mi * (16 * GSTR2) + kk * 32, af[mi]);
#pragma unroll
            for (int p = 0; p < 2; ++p) {
                uint32_t r4[4];
                ldsm_x4(bBase + p * (16 * GSTR2) + kk * 32, r4);
                bw[2 * p][0] = r4[0]; bw[2 * p][1] = r4[1];
                bw[2 * p + 1][0] = r4[2]; bw[2 * p + 1][1] = r4[3];
            }
#pragma unroll
            for (int mi = 0; mi < 2; ++mi)
#pragma unroll
                for (int ni = 0; ni < 4; ++ni)
                    mma16816h(acc[mi][ni], af[mi], bw[ni]);
        }
    }

    int r = lane >> 2, c2 = (lane & 3) * 2;
    int warpM = m0 + mw * 32, warpN = n0 + nw * 32;
#pragma unroll
    for (int mi = 0; mi < 2; ++mi)
#pragma unroll
        for (int ni = 0; ni < 4; ++ni) {
            int n = warpN + ni * 8 + c2;
#pragma unroll
            for (int h = 0; h < 2; ++h) {
                int m = warpM + mi * 16 + r + h * 8;
                float v0 = acc[mi][ni][h * 2 + 0];
                float v1 = acc[mi][ni][h * 2 + 1];
                if (OUTM == 1) {
                    float2 bb = *(const float2*)(bias + n);
                    v0 = fmaxf(v0 + bb.x, 0.f);
                    v1 = fmaxf(v1 + bb.y, 0.f);
                }
                *(__half2*)(outH + (size_t)m * ldo + n) = __floats2half2_rn(v0, v1);
            }
        }
}

// ======================= pairwise relu outer-sum mean, i-split x4 =======================
// block (chunk, b, z): i in [z*16, z*16+16), channels [chunk*64, chunk*64+64).
// writes fp32 partial to mp[z][b][512]. Deterministic (no atomics).
__global__ __launch_bounds__(256) void pairwise_kernel(const __half* __restrict__ ABh,
                                                       const float* __restrict__ b1,
                                                       float* __restrict__ mp) {
    __shared__ float As[64][64];
    __shared__ float Bs[16][64];
    __shared__ float part[4][64];
    int t = threadIdx.x;
    int chunk = blockIdx.x;
    int b = blockIdx.y;
    int z = blockIdx.z;
    int c0 = chunk * 64;
    const __half* base = ABh + (size_t)b * 64 * 1024;

    // load A (all 64 j-rows, this channel chunk)
#pragma unroll
    for (int q = 0; q < 2; q++) {
        int u = t + q * 256;              // 0..511
        int row = u >> 3;                 // 0..63
        int seg = u & 7;
        const __half2* pa = (const __half2*)(base + (size_t)row * 1024 + c0 + seg * 8);
#pragma unroll
        for (int j = 0; j < 4; ++j) {
            float2 fa = __half22float2(pa[j]);
            As[row][seg * 8 + 2 * j + 0] = fa.x;
            As[row][seg * 8 + 2 * j + 1] = fa.y;
        }
    }
    // load B (this block's 16 i-rows)
    if (t < 128) {
        int row = t >> 3;                 // 0..15
        int seg = t & 7;
        const __half2* pb = (const __half2*)(base + (size_t)(z * 16 + row) * 1024 + 512 + c0 + seg * 8);
#pragma unroll
        for (int j = 0; j < 4; ++j) {
            float2 fb = __half22float2(pb[j]);
            Bs[row][seg * 8 + 2 * j + 0] = fb.x;
            Bs[row][seg * 8 + 2 * j + 1] = fb.y;
        }
    }
    __syncthreads();

    int c = t & 63;
    int ig = t >> 6;                      // 0..3 -> 4 i's each
    float bias = b1[c0 + c];
    float acc = 0.f;
#pragma unroll
    for (int i = 0; i < 4; i++) {
        float bb = Bs[ig * 4 + i][c] + bias;
#pragma unroll
        for (int j = 0; j < 64; j++)
            acc += fmaxf(As[j][c] + bb, 0.f);
    }
    part[ig][c] = acc;
    __syncthreads();
    if (t < 64) {
        float s = part[0][t] + part[1][t] + part[2][t] + part[3][t];
        mp[((size_t)z * 16 + b) * 512 + c0 + t] = s * (1.0f / 4096.0f);
    }
}

// ======================= final 512 -> 2048 (sums 4 pairwise partials) =======================
__global__ __launch_bounds__(256) void final_kernel(const float* __restrict__ mp,
                                                    const float* __restrict__ w2,
                                                    const float* __restrict__ b2,
                                                    float* __restrict__ out) {
    __shared__ float sm[16 * 512];
    int t = threadIdx.x;
    for (int i = t; i < 16 * 512; i += 256)
        sm[i] = mp[i] + mp[8192 + i] + mp[16384 + i] + mp[24576 + i];
    __syncthreads();

    int warp = t >> 5, lane = t & 31;
    int o = blockIdx.x * 8 + warp;
    float acc[16];
#pragma unroll
    for (int b = 0; b < 16; b++) acc[b] = 0.f;
    const float* wrow = w2 + (size_t)o * 512;
#pragma unroll
    for (int kc = 0; kc < 16; kc++) {
        int k = kc * 32 + lane;
        float wv = wrow[k];
#pragma unroll
        for (int b = 0; b < 16; b++) acc[b] = fmaf(wv, sm[b * 512 + k], acc[b]);
    }
#pragma unroll
    for (int b = 0; b < 16; b++) {
        float v = acc[b];
#pragma unroll
        for (int s = 16; s > 0; s >>= 1) v += __shfl_xor_sync(0xffffffffu, v, s);
        if (lane == 0) out[b * 2048 + o] = v + b2[o];
    }
}

// ======================= launch =======================
extern "C" void kernel_launch(void* const* d_in, const int* in_sizes, int n_in,
                              void* d_out, int out_size) {
    (void)in_sizes; (void)n_in; (void)out_size;
    const float* x   = (const float*)d_in[0];
    const float* e1w = (const float*)d_in[1];
    const float* e1b = (const float*)d_in[2];
    const float* e2w = (const float*)d_in[3];
    const float* e2b = (const float*)d_in[4];
    const float* r1w = (const float*)d_in[5];
    const float* r1b = (const float*)d_in[6];
    const float* r2w = (const float*)d_in[7];
    const float* r2b = (const float*)d_in[8];
    const float* r3w = (const float*)d_in[9];
    const float* r3b = (const float*)d_in[10];
    const float* w1  = (const float*)d_in[11];
    const float* b1  = (const float*)d_in[12];
    const float* w2  = (const float*)d_in[13];
    const float* b2  = (const float*)d_in[14];
    float* out = (float*)d_out;

    __half *e128, *e256, *e512, *e1024, *r1wq, *r2wq, *r3wq, *wab, *ABh;
    float *mp;
    cudaGetSymbolAddress((void**)&e128, g_e128);
    cudaGetSymbolAddress((void**)&e256, g_e256);
    cudaGetSymbolAddress((void**)&e512, g_e512);
    cudaGetSymbolAddress((void**)&e1024, g_e1024);
    cudaGetSymbolAddress((void**)&r1wq, g_r1w);
    cudaGetSymbolAddress((void**)&r2wq, g_r2w);
    cudaGetSymbolAddress((void**)&r3wq, g_r3w);
    cudaGetSymbolAddress((void**)&wab, g_wab);
    cudaGetSymbolAddress((void**)&ABh, g_ABh);
    cudaGetSymbolAddress((void**)&mp, g_mp);

    cudaFuncSetAttribute(hgemm_small, cudaFuncAttributeMaxDynamicSharedMemorySize, S_SMEM);
    cudaFuncSetAttribute(hgemm_big<1>, cudaFuncAttributeMaxDynamicSharedMemorySize, B_SMEM);
    cudaFuncSetAttribute(hgemm_big<0>, cudaFuncAttributeMaxDynamicSharedMemorySize, B_SMEM);

    // fused prep: fp16 converts + embedding (one launch)
    prep_kernel<<<2208, 256>>>(r1w, (__half2*)r1wq, r2w, (__half2*)r2wq,
                               r3w, (__half2*)r3wq, w1, (__half2*)wab,
                               x, e1w, e1b, e2w, e2b, e128);

    // r1: 128 -> 256 (bias+relu), 64 CTAs
    hgemm_small<<<dim3(4, 16), 128, S_SMEM>>>(e128, r1wq, r1b, 128, e256, 256);
    // r2: 256 -> 512, 128 CTAs
    hgemm_small<<<dim3(8, 16), 128, S_SMEM>>>(e256, r2wq, r2b, 256, e512, 512);
    // r3: 512 -> 1024, K-chunk 128, 128 CTAs
    hgemm_big<1><<<dim3(16, 8), 256, B_SMEM>>>(e512, r3wq, r3b, 512, e1024, 1024);
    // A|B fused: 1024 -> 1024 (raw fp16 out), 128 CTAs
    hgemm_big<0><<<dim3(16, 8), 256, B_SMEM>>>(e1024, wab, nullptr, 1024, ABh, 1024);

    // pairwise mean, i-split x4 -> partials mp[4][16][512]
    pairwise_kernel<<<dim3(8, 16, 4), 256>>>(ABh, b1, mp);

    // final 512 -> 2048 (sums partials)
    final_kernel<<<2048 / 8, 256>>>(mp, w2, b2, out);
}